// round 1
// baseline (speedup 1.0000x reference)
#include <cuda_runtime.h>
#include <math.h>

// ---------------- problem constants ----------------
#define FRAMES 4096      // B*T = 32*128
#define CIN0   9
#define NF     64
#define HW     121       // 11*11
#define PLANE  169       // 13*13 padded
#define FCK    7744      // 64*121
#define NT_CONV 176      // 16 oc-groups * 11 rows

// ---------------- global scratch (static, no runtime alloc) ----------------
__device__ float g_conv_out[(size_t)FRAMES * FCK];   // 127 MB
__device__ float g_feats[(size_t)FRAMES * 64];
__device__ float g_xg[(size_t)FRAMES * 256];
__device__ float g_lstm[(size_t)FRAMES * 64];

// =====================================================================
// Kernel 1: fused 8-layer conv stack, one CTA per frame.
// smem: in_s[64*169] activations (padded 13x13), ws[64*64*9] weights, bs[64]
// =====================================================================
__global__ __launch_bounds__(NT_CONV, 1)
void conv_stack_kernel(const float* __restrict__ x,
                       const float* __restrict__ c0w, const float* __restrict__ c0b,
                       const float* __restrict__ cws, const float* __restrict__ cbs)
{
    extern __shared__ float sm[];
    float* in_s = sm;                   // 64*169
    float* ws   = sm + 64 * PLANE;      // 36864
    float* bs   = ws + 36864;           // 64

    const int f   = blockIdx.x;
    const int tid = threadIdx.x;
    const int row = tid % 11;           // output row 0..10
    const int ocg = tid / 11;           // 0..15, handles oc = ocg*4 .. +3

    // zero activation buffer (halo stays zero forever)
    for (int i = tid; i < 64 * PLANE; i += NT_CONV) in_s[i] = 0.f;
    __syncthreads();

    // load input frame (9 channels) into padded interior
    const float* xf = x + (size_t)f * CIN0 * HW;
    for (int i = tid; i < CIN0 * HW; i += NT_CONV) {
        int ch = i / HW, pix = i % HW;
        int r = pix / 11, c = pix % 11;
        in_s[ch * PLANE + (r + 1) * 13 + (c + 1)] = xf[i];
    }

    for (int layer = 0; layer < 8; ++layer) {
        // ---- stage weights+bias into smem ----
        if (layer == 0) {
            for (int i = tid; i < 64 * CIN0 * 9; i += NT_CONV) ws[i] = c0w[i];
            if (tid < 64) bs[tid] = c0b[tid];
        } else {
            const float4* w4 = (const float4*)(cws + (size_t)(layer - 1) * 36864);
            float4* d4 = (float4*)ws;
            for (int i = tid; i < 36864 / 4; i += NT_CONV) d4[i] = w4[i];
            if (tid < 64) bs[tid] = cbs[(layer - 1) * 64 + tid];
        }
        __syncthreads();

        const int cin = (layer == 0) ? CIN0 : 64;
        float acc[4][11];
#pragma unroll
        for (int j = 0; j < 4; ++j) {
            float bias = bs[ocg * 4 + j];
#pragma unroll
            for (int xx = 0; xx < 11; ++xx) acc[j][xx] = bias;
        }

        for (int ic = 0; ic < cin; ++ic) {
            float r0[13], r1[13], r2[13];
            const float* p = in_s + ic * PLANE + row * 13;
#pragma unroll
            for (int k = 0; k < 13; ++k) { r0[k] = p[k]; r1[k] = p[13 + k]; r2[k] = p[26 + k]; }
#pragma unroll
            for (int j = 0; j < 4; ++j) {
                const int oc = ocg * 4 + j;
                const float* wp = ws + (oc * cin + ic) * 9;
                float w0 = wp[0], w1 = wp[1], w2 = wp[2];
                float w3 = wp[3], w4 = wp[4], w5 = wp[5];
                float w6 = wp[6], w7 = wp[7], w8 = wp[8];
#pragma unroll
                for (int xx = 0; xx < 11; ++xx) {
                    float s = acc[j][xx];
                    s = fmaf(w0, r0[xx    ], s);
                    s = fmaf(w1, r0[xx + 1], s);
                    s = fmaf(w2, r0[xx + 2], s);
                    s = fmaf(w3, r1[xx    ], s);
                    s = fmaf(w4, r1[xx + 1], s);
                    s = fmaf(w5, r1[xx + 2], s);
                    s = fmaf(w6, r2[xx    ], s);
                    s = fmaf(w7, r2[xx + 1], s);
                    s = fmaf(w8, r2[xx + 2], s);
                    acc[j][xx] = s;
                }
            }
        }
        __syncthreads();   // all reads of in_s / ws complete

        if (layer < 7) {
#pragma unroll
            for (int j = 0; j < 4; ++j) {
                const int oc = ocg * 4 + j;
#pragma unroll
                for (int xx = 0; xx < 11; ++xx)
                    in_s[oc * PLANE + (row + 1) * 13 + (xx + 1)] = fmaxf(acc[j][xx], 0.f);
            }
        } else {
            float* of = g_conv_out + (size_t)f * FCK;
#pragma unroll
            for (int j = 0; j < 4; ++j) {
                const int oc = ocg * 4 + j;
#pragma unroll
                for (int xx = 0; xx < 11; ++xx)
                    of[oc * HW + row * 11 + xx] = fmaxf(acc[j][xx], 0.f);
            }
        }
        __syncthreads();
    }
}

// =====================================================================
// Kernel 2: FC GEMM  feats[4096,64] = relu(conv_out[4096,7744] @ fc_w[64,7744]^T + b)
// CTA tile 64m x 64n, K-tile 32. 256 threads, 4x4 microtile.
// =====================================================================
__global__ __launch_bounds__(256)
void fc_kernel(const float* __restrict__ W, const float* __restrict__ b)
{
    __shared__ float As[64][33];
    __shared__ float Ws[64][33];
    const int m0 = blockIdx.x * 64;
    const int tid = threadIdx.x;
    const int tx = tid & 15, ty = tid >> 4;
    const float* A = g_conv_out;

    float acc[4][4] = {};
    for (int k0 = 0; k0 < FCK; k0 += 32) {
#pragma unroll
        for (int v = 0; v < 2; ++v) {
            int idx = tid + v * 256;
            int r = idx >> 3, c4 = (idx & 7) << 2;
            float4 a4 = *(const float4*)&A[(size_t)(m0 + r) * FCK + k0 + c4];
            As[r][c4] = a4.x; As[r][c4 + 1] = a4.y; As[r][c4 + 2] = a4.z; As[r][c4 + 3] = a4.w;
            float4 w4 = *(const float4*)&W[(size_t)r * FCK + k0 + c4];
            Ws[r][c4] = w4.x; Ws[r][c4 + 1] = w4.y; Ws[r][c4 + 2] = w4.z; Ws[r][c4 + 3] = w4.w;
        }
        __syncthreads();
#pragma unroll
        for (int kk = 0; kk < 32; ++kk) {
            float a[4], w[4];
#pragma unroll
            for (int i = 0; i < 4; ++i) a[i] = As[ty * 4 + i][kk];
#pragma unroll
            for (int j = 0; j < 4; ++j) w[j] = Ws[tx * 4 + j][kk];
#pragma unroll
            for (int i = 0; i < 4; ++i)
#pragma unroll
                for (int j = 0; j < 4; ++j) acc[i][j] = fmaf(a[i], w[j], acc[i][j]);
        }
        __syncthreads();
    }
#pragma unroll
    for (int i = 0; i < 4; ++i) {
        int m = m0 + ty * 4 + i;
#pragma unroll
        for (int j = 0; j < 4; ++j) {
            int n = tx * 4 + j;
            g_feats[(size_t)m * 64 + n] = fmaxf(acc[i][j] + b[n], 0.f);
        }
    }
}

// =====================================================================
// Kernel 3: precompute input gates  xg[4096,256] = feats @ w_ih^T + b_ih + b_hh
// 64 CTAs x 256 threads; thread g holds w_ih row in 64 registers.
// =====================================================================
__global__ __launch_bounds__(256)
void xgates_kernel(const float* __restrict__ w_ih,
                   const float* __restrict__ b_ih, const float* __restrict__ b_hh)
{
    __shared__ float fs[64][64];
    const int f0 = blockIdx.x * 64;
    const int g = threadIdx.x;
    float w[64];
#pragma unroll
    for (int k = 0; k < 64; ++k) w[k] = w_ih[g * 64 + k];
    for (int i = g; i < 64 * 64; i += 256) fs[i / 64][i % 64] = g_feats[(size_t)f0 * 64 + i];
    __syncthreads();
    const float bias = b_ih[g] + b_hh[g];
    for (int f = 0; f < 64; ++f) {
        float s = bias;
#pragma unroll
        for (int k = 0; k < 64; ++k) s = fmaf(w[k], fs[f][k], s);
        g_xg[(size_t)(f0 + f) * 256 + g] = s;
    }
}

// =====================================================================
// Kernel 4: recurrent LSTM. 32 CTAs (one per batch row), 256 threads (one per gate).
// =====================================================================
__global__ __launch_bounds__(256)
void lstm_kernel(const float* __restrict__ w_hh)
{
    __shared__ float h_s[64];
    __shared__ float g_s[256];
    const int b = blockIdx.x;
    const int g = threadIdx.x;
    float w[64];
#pragma unroll
    for (int k = 0; k < 64; ++k) w[k] = w_hh[g * 64 + k];
    float c = 0.f;
    if (g < 64) h_s[g] = 0.f;
    __syncthreads();

    const float* xgb = g_xg + (size_t)b * 128 * 256;
    float* lob = g_lstm + (size_t)b * 128 * 64;
    for (int t = 0; t < 128; ++t) {
        float s = xgb[t * 256 + g];
#pragma unroll
        for (int k = 0; k < 64; ++k) s = fmaf(w[k], h_s[k], s);
        g_s[g] = s;
        __syncthreads();
        if (g < 64) {
            float ig = 1.f / (1.f + expf(-g_s[g]));
            float fg = 1.f / (1.f + expf(-g_s[64 + g]));
            float gg = tanhf(g_s[128 + g]);
            float og = 1.f / (1.f + expf(-g_s[192 + g]));
            c = fg * c + ig * gg;
            float h = og * tanhf(c);
            lob[t * 64 + g] = h;
            h_s[g] = h;
        }
        __syncthreads();
    }
}

// =====================================================================
// Kernel 5: fused policy/value heads. 128 CTAs x 32 frames each, 256 threads.
// threads 0..127: p1 rows; 128..255: v1 rows (weights register-resident).
// Stage 2: warps 0..5 -> p2 outputs, warp 6 -> v2.
// =====================================================================
__global__ __launch_bounds__(256)
void heads_kernel(const float* __restrict__ p1w, const float* __restrict__ p1b,
                  const float* __restrict__ p2w, const float* __restrict__ p2b,
                  const float* __restrict__ v1w, const float* __restrict__ v1b,
                  const float* __restrict__ v2w, const float* __restrict__ v2b,
                  float* __restrict__ out)
{
    __shared__ float h_s[32][64];
    __shared__ float p2s[6 * 128];
    __shared__ float v2s[128];
    __shared__ float u_s[256];

    const int f0 = blockIdx.x * 32;
    const int t = threadIdx.x;

    const float* wsrc = (t < 128) ? (p1w + t * 64) : (v1w + (t - 128) * 64);
    float w[64];
#pragma unroll
    for (int k = 0; k < 64; ++k) w[k] = wsrc[k];
    const float bias = (t < 128) ? p1b[t] : v1b[t - 128];

    for (int i = t; i < 32 * 64; i += 256) h_s[i / 64][i % 64] = g_lstm[(size_t)f0 * 64 + i];
    for (int i = t; i < 768; i += 256) p2s[i] = p2w[i];
    if (t < 128) v2s[t] = v2w[t];
    __syncthreads();

    const int warp = t >> 5, lane = t & 31;
    for (int fi = 0; fi < 32; ++fi) {
        float s = bias;
#pragma unroll
        for (int k = 0; k < 64; ++k) s = fmaf(w[k], h_s[fi][k], s);
        u_s[t] = fmaxf(s, 0.f);
        __syncthreads();

        const int f = f0 + fi;
        if (warp < 6) {
            float s2 = 0.f;
#pragma unroll
            for (int j = 0; j < 4; ++j)
                s2 = fmaf(p2s[warp * 128 + j * 32 + lane], u_s[j * 32 + lane], s2);
            for (int off = 16; off; off >>= 1) s2 += __shfl_down_sync(0xffffffffu, s2, off);
            if (lane == 0) out[f * 6 + warp] = s2 + p2b[warp];
        } else if (warp == 6) {
            float s2 = 0.f;
#pragma unroll
            for (int j = 0; j < 4; ++j)
                s2 = fmaf(v2s[j * 32 + lane], u_s[128 + j * 32 + lane], s2);
            for (int off = 16; off; off >>= 1) s2 += __shfl_down_sync(0xffffffffu, s2, off);
            if (lane == 0) out[FRAMES * 6 + f] = s2 + v2b[0];
        }
        __syncthreads();
    }
}

// =====================================================================
extern "C" void kernel_launch(void* const* d_in, const int* in_sizes, int n_in,
                              void* d_out, int out_size)
{
    const float* x    = (const float*)d_in[0];
    const float* c0w  = (const float*)d_in[1];
    const float* c0b  = (const float*)d_in[2];
    const float* cws  = (const float*)d_in[3];
    const float* cbs  = (const float*)d_in[4];
    const float* fcw  = (const float*)d_in[5];
    const float* fcb  = (const float*)d_in[6];
    const float* wih  = (const float*)d_in[7];
    const float* whh  = (const float*)d_in[8];
    const float* bih  = (const float*)d_in[9];
    const float* bhh  = (const float*)d_in[10];
    const float* p1w  = (const float*)d_in[11];
    const float* p1b  = (const float*)d_in[12];
    const float* p2w  = (const float*)d_in[13];
    const float* p2b  = (const float*)d_in[14];
    const float* v1w  = (const float*)d_in[15];
    const float* v1b  = (const float*)d_in[16];
    const float* v2w  = (const float*)d_in[17];
    const float* v2b  = (const float*)d_in[18];
    float* out = (float*)d_out;

    const int conv_smem = (64 * PLANE + 36864 + 64) * (int)sizeof(float); // ~186.5 KB
    cudaFuncSetAttribute(conv_stack_kernel,
                         cudaFuncAttributeMaxDynamicSharedMemorySize, conv_smem);

    conv_stack_kernel<<<FRAMES, NT_CONV, conv_smem>>>(x, c0w, c0b, cws, cbs);
    fc_kernel<<<FRAMES / 64, 256>>>(fcw, fcb);
    xgates_kernel<<<FRAMES / 64, 256>>>(wih, bih, bhh);
    lstm_kernel<<<32, 256>>>(whh);
    heads_kernel<<<FRAMES / 32, 256>>>(p1w, p1b, p2w, p2b, v1w, v1b, v2w, v2b, out);
}

// round 2
// speedup vs baseline: 1.0004x; 1.0004x over previous
#include <cuda_runtime.h>
#include <math.h>

// ---------------- problem constants ----------------
#define FRAMES 4096      // B*T = 32*128
#define CIN0   9
#define NF     64
#define HW     121       // 11*11
#define PLANE  169       // 13*13 padded
#define FCK    7744      // 64*121
#define NT_CONV 176      // 16 oc-groups * 11 rows

// ---------------- global scratch (static, no runtime alloc) ----------------
__device__ float g_conv_out[(size_t)FRAMES * FCK];   // 127 MB
__device__ float g_feats[(size_t)FRAMES * 64];
__device__ float g_xg[(size_t)FRAMES * 256];
__device__ float g_lstm[(size_t)FRAMES * 64];

// =====================================================================
// Kernel 1: fused 8-layer conv stack, one CTA per frame.
// smem: in_s[64*169] activations (padded 13x13), ws[64*64*9] weights, bs[64]
// =====================================================================
__global__ __launch_bounds__(NT_CONV, 1)
void conv_stack_kernel(const float* __restrict__ x,
                       const float* __restrict__ c0w, const float* __restrict__ c0b,
                       const float* __restrict__ cws, const float* __restrict__ cbs)
{
    extern __shared__ float sm[];
    float* in_s = sm;                   // 64*169
    float* ws   = sm + 64 * PLANE;      // 36864
    float* bs   = ws + 36864;           // 64

    const int f   = blockIdx.x;
    const int tid = threadIdx.x;
    const int row = tid % 11;           // output row 0..10
    const int ocg = tid / 11;           // 0..15, handles oc = ocg*4 .. +3

    // zero activation buffer (halo stays zero forever)
    for (int i = tid; i < 64 * PLANE; i += NT_CONV) in_s[i] = 0.f;
    __syncthreads();

    // load input frame (9 channels) into padded interior
    const float* xf = x + (size_t)f * CIN0 * HW;
    for (int i = tid; i < CIN0 * HW; i += NT_CONV) {
        int ch = i / HW, pix = i % HW;
        int r = pix / 11, c = pix % 11;
        in_s[ch * PLANE + (r + 1) * 13 + (c + 1)] = xf[i];
    }

    for (int layer = 0; layer < 8; ++layer) {
        // ---- stage weights+bias into smem ----
        if (layer == 0) {
            for (int i = tid; i < 64 * CIN0 * 9; i += NT_CONV) ws[i] = c0w[i];
            if (tid < 64) bs[tid] = c0b[tid];
        } else {
            const float4* w4 = (const float4*)(cws + (size_t)(layer - 1) * 36864);
            float4* d4 = (float4*)ws;
            for (int i = tid; i < 36864 / 4; i += NT_CONV) d4[i] = w4[i];
            if (tid < 64) bs[tid] = cbs[(layer - 1) * 64 + tid];
        }
        __syncthreads();

        const int cin = (layer == 0) ? CIN0 : 64;
        float acc[4][11];
#pragma unroll
        for (int j = 0; j < 4; ++j) {
            float bias = bs[ocg * 4 + j];
#pragma unroll
            for (int xx = 0; xx < 11; ++xx) acc[j][xx] = bias;
        }

        for (int ic = 0; ic < cin; ++ic) {
            float r0[13], r1[13], r2[13];
            const float* p = in_s + ic * PLANE + row * 13;
#pragma unroll
            for (int k = 0; k < 13; ++k) { r0[k] = p[k]; r1[k] = p[13 + k]; r2[k] = p[26 + k]; }
#pragma unroll
            for (int j = 0; j < 4; ++j) {
                const int oc = ocg * 4 + j;
                const float* wp = ws + (oc * cin + ic) * 9;
                float w0 = wp[0], w1 = wp[1], w2 = wp[2];
                float w3 = wp[3], w4 = wp[4], w5 = wp[5];
                float w6 = wp[6], w7 = wp[7], w8 = wp[8];
#pragma unroll
                for (int xx = 0; xx < 11; ++xx) {
                    float s = acc[j][xx];
                    s = fmaf(w0, r0[xx    ], s);
                    s = fmaf(w1, r0[xx + 1], s);
                    s = fmaf(w2, r0[xx + 2], s);
                    s = fmaf(w3, r1[xx    ], s);
                    s = fmaf(w4, r1[xx + 1], s);
                    s = fmaf(w5, r1[xx + 2], s);
                    s = fmaf(w6, r2[xx    ], s);
                    s = fmaf(w7, r2[xx + 1], s);
                    s = fmaf(w8, r2[xx + 2], s);
                    acc[j][xx] = s;
                }
            }
        }
        __syncthreads();   // all reads of in_s / ws complete

        if (layer < 7) {
#pragma unroll
            for (int j = 0; j < 4; ++j) {
                const int oc = ocg * 4 + j;
#pragma unroll
                for (int xx = 0; xx < 11; ++xx)
                    in_s[oc * PLANE + (row + 1) * 13 + (xx + 1)] = fmaxf(acc[j][xx], 0.f);
            }
        } else {
            float* of = g_conv_out + (size_t)f * FCK;
#pragma unroll
            for (int j = 0; j < 4; ++j) {
                const int oc = ocg * 4 + j;
#pragma unroll
                for (int xx = 0; xx < 11; ++xx)
                    of[oc * HW + row * 11 + xx] = fmaxf(acc[j][xx], 0.f);
            }
        }
        __syncthreads();
    }
}

// =====================================================================
// Kernel 2: FC GEMM  feats[4096,64] = relu(conv_out[4096,7744] @ fc_w[64,7744]^T + b)
// CTA tile 64m x 64n, K-tile 32. 256 threads, 4x4 microtile.
// =====================================================================
__global__ __launch_bounds__(256)
void fc_kernel(const float* __restrict__ W, const float* __restrict__ b)
{
    __shared__ float As[64][33];
    __shared__ float Ws[64][33];
    const int m0 = blockIdx.x * 64;
    const int tid = threadIdx.x;
    const int tx = tid & 15, ty = tid >> 4;
    const float* A = g_conv_out;

    float acc[4][4] = {};
    for (int k0 = 0; k0 < FCK; k0 += 32) {
#pragma unroll
        for (int v = 0; v < 2; ++v) {
            int idx = tid + v * 256;
            int r = idx >> 3, c4 = (idx & 7) << 2;
            float4 a4 = *(const float4*)&A[(size_t)(m0 + r) * FCK + k0 + c4];
            As[r][c4] = a4.x; As[r][c4 + 1] = a4.y; As[r][c4 + 2] = a4.z; As[r][c4 + 3] = a4.w;
            float4 w4 = *(const float4*)&W[(size_t)r * FCK + k0 + c4];
            Ws[r][c4] = w4.x; Ws[r][c4 + 1] = w4.y; Ws[r][c4 + 2] = w4.z; Ws[r][c4 + 3] = w4.w;
        }
        __syncthreads();
#pragma unroll
        for (int kk = 0; kk < 32; ++kk) {
            float a[4], w[4];
#pragma unroll
            for (int i = 0; i < 4; ++i) a[i] = As[ty * 4 + i][kk];
#pragma unroll
            for (int j = 0; j < 4; ++j) w[j] = Ws[tx * 4 + j][kk];
#pragma unroll
            for (int i = 0; i < 4; ++i)
#pragma unroll
                for (int j = 0; j < 4; ++j) acc[i][j] = fmaf(a[i], w[j], acc[i][j]);
        }
        __syncthreads();
    }
#pragma unroll
    for (int i = 0; i < 4; ++i) {
        int m = m0 + ty * 4 + i;
#pragma unroll
        for (int j = 0; j < 4; ++j) {
            int n = tx * 4 + j;
            g_feats[(size_t)m * 64 + n] = fmaxf(acc[i][j] + b[n], 0.f);
        }
    }
}

// =====================================================================
// Kernel 3: precompute input gates  xg[4096,256] = feats @ w_ih^T + b_ih + b_hh
// 64 CTAs x 256 threads; thread g holds w_ih row in 64 registers.
// =====================================================================
__global__ __launch_bounds__(256)
void xgates_kernel(const float* __restrict__ w_ih,
                   const float* __restrict__ b_ih, const float* __restrict__ b_hh)
{
    __shared__ float fs[64][64];
    const int f0 = blockIdx.x * 64;
    const int g = threadIdx.x;
    float w[64];
#pragma unroll
    for (int k = 0; k < 64; ++k) w[k] = w_ih[g * 64 + k];
    for (int i = g; i < 64 * 64; i += 256) fs[i / 64][i % 64] = g_feats[(size_t)f0 * 64 + i];
    __syncthreads();
    const float bias = b_ih[g] + b_hh[g];
    for (int f = 0; f < 64; ++f) {
        float s = bias;
#pragma unroll
        for (int k = 0; k < 64; ++k) s = fmaf(w[k], fs[f][k], s);
        g_xg[(size_t)(f0 + f) * 256 + g] = s;
    }
}

// =====================================================================
// Kernel 4: recurrent LSTM. 32 CTAs (one per batch row), 256 threads (one per gate).
// =====================================================================
__global__ __launch_bounds__(256)
void lstm_kernel(const float* __restrict__ w_hh)
{
    __shared__ float h_s[64];
    __shared__ float g_s[256];
    const int b = blockIdx.x;
    const int g = threadIdx.x;
    float w[64];
#pragma unroll
    for (int k = 0; k < 64; ++k) w[k] = w_hh[g * 64 + k];
    float c = 0.f;
    if (g < 64) h_s[g] = 0.f;
    __syncthreads();

    const float* xgb = g_xg + (size_t)b * 128 * 256;
    float* lob = g_lstm + (size_t)b * 128 * 64;
    for (int t = 0; t < 128; ++t) {
        float s = xgb[t * 256 + g];
#pragma unroll
        for (int k = 0; k < 64; ++k) s = fmaf(w[k], h_s[k], s);
        g_s[g] = s;
        __syncthreads();
        if (g < 64) {
            float ig = 1.f / (1.f + expf(-g_s[g]));
            float fg = 1.f / (1.f + expf(-g_s[64 + g]));
            float gg = tanhf(g_s[128 + g]);
            float og = 1.f / (1.f + expf(-g_s[192 + g]));
            c = fg * c + ig * gg;
            float h = og * tanhf(c);
            lob[t * 64 + g] = h;
            h_s[g] = h;
        }
        __syncthreads();
    }
}

// =====================================================================
// Kernel 5: fused policy/value heads. 128 CTAs x 32 frames each, 256 threads.
// threads 0..127: p1 rows; 128..255: v1 rows (weights register-resident).
// Stage 2: warps 0..5 -> p2 outputs, warp 6 -> v2.
// =====================================================================
__global__ __launch_bounds__(256)
void heads_kernel(const float* __restrict__ p1w, const float* __restrict__ p1b,
                  const float* __restrict__ p2w, const float* __restrict__ p2b,
                  const float* __restrict__ v1w, const float* __restrict__ v1b,
                  const float* __restrict__ v2w, const float* __restrict__ v2b,
                  float* __restrict__ out)
{
    __shared__ float h_s[32][64];
    __shared__ float p2s[6 * 128];
    __shared__ float v2s[128];
    __shared__ float u_s[256];

    const int f0 = blockIdx.x * 32;
    const int t = threadIdx.x;

    const float* wsrc = (t < 128) ? (p1w + t * 64) : (v1w + (t - 128) * 64);
    float w[64];
#pragma unroll
    for (int k = 0; k < 64; ++k) w[k] = wsrc[k];
    const float bias = (t < 128) ? p1b[t] : v1b[t - 128];

    for (int i = t; i < 32 * 64; i += 256) h_s[i / 64][i % 64] = g_lstm[(size_t)f0 * 64 + i];
    for (int i = t; i < 768; i += 256) p2s[i] = p2w[i];
    if (t < 128) v2s[t] = v2w[t];
    __syncthreads();

    const int warp = t >> 5, lane = t & 31;
    for (int fi = 0; fi < 32; ++fi) {
        float s = bias;
#pragma unroll
        for (int k = 0; k < 64; ++k) s = fmaf(w[k], h_s[fi][k], s);
        u_s[t] = fmaxf(s, 0.f);
        __syncthreads();

        const int f = f0 + fi;
        if (warp < 6) {
            float s2 = 0.f;
#pragma unroll
            for (int j = 0; j < 4; ++j)
                s2 = fmaf(p2s[warp * 128 + j * 32 + lane], u_s[j * 32 + lane], s2);
            for (int off = 16; off; off >>= 1) s2 += __shfl_down_sync(0xffffffffu, s2, off);
            if (lane == 0) out[f * 6 + warp] = s2 + p2b[warp];
        } else if (warp == 6) {
            float s2 = 0.f;
#pragma unroll
            for (int j = 0; j < 4; ++j)
                s2 = fmaf(v2s[j * 32 + lane], u_s[128 + j * 32 + lane], s2);
            for (int off = 16; off; off >>= 1) s2 += __shfl_down_sync(0xffffffffu, s2, off);
            if (lane == 0) out[FRAMES * 6 + f] = s2 + v2b[0];
        }
        __syncthreads();
    }
}

// =====================================================================
extern "C" void kernel_launch(void* const* d_in, const int* in_sizes, int n_in,
                              void* d_out, int out_size)
{
    const float* x    = (const float*)d_in[0];
    const float* c0w  = (const float*)d_in[1];
    const float* c0b  = (const float*)d_in[2];
    const float* cws  = (const float*)d_in[3];
    const float* cbs  = (const float*)d_in[4];
    const float* fcw  = (const float*)d_in[5];
    const float* fcb  = (const float*)d_in[6];
    const float* wih  = (const float*)d_in[7];
    const float* whh  = (const float*)d_in[8];
    const float* bih  = (const float*)d_in[9];
    const float* bhh  = (const float*)d_in[10];
    const float* p1w  = (const float*)d_in[11];
    const float* p1b  = (const float*)d_in[12];
    const float* p2w  = (const float*)d_in[13];
    const float* p2b  = (const float*)d_in[14];
    const float* v1w  = (const float*)d_in[15];
    const float* v1b  = (const float*)d_in[16];
    const float* v2w  = (const float*)d_in[17];
    const float* v2b  = (const float*)d_in[18];
    float* out = (float*)d_out;

    const int conv_smem = (64 * PLANE + 36864 + 64) * (int)sizeof(float); // ~186.5 KB
    cudaFuncSetAttribute(conv_stack_kernel,
                         cudaFuncAttributeMaxDynamicSharedMemorySize, conv_smem);

    conv_stack_kernel<<<FRAMES, NT_CONV, conv_smem>>>(x, c0w, c0b, cws, cbs);
    fc_kernel<<<FRAMES / 64, 256>>>(fcw, fcb);
    xgates_kernel<<<FRAMES / 64, 256>>>(wih, bih, bhh);
    lstm_kernel<<<32, 256>>>(whh);
    heads_kernel<<<FRAMES / 32, 256>>>(p1w, p1b, p2w, p2b, v1w, v1b, v2w, v2b, out);
}

// round 3
// speedup vs baseline: 2.6654x; 2.6643x over previous
#include <cuda_runtime.h>
#include <cuda_bf16.h>
#include <math.h>

// ---------------- problem constants ----------------
#define FRAMES 4096      // B*T
#define HW     121
#define FCK    7744
#define XSTRIDE 72       // padded X row stride (bf16 elems) -> 144B, conflict-free
#define XROWS   172      // 13x13=169 plane + 3 overread pad rows
#define BFRAG_PER_LAYER 18432   // u32: 9 taps * 4 ksteps * 8 ntiles * 32 lanes * 2 regs

// ---------------- global scratch ----------------
__device__ float g_conv_out[(size_t)FRAMES * FCK];
__device__ float g_feats[(size_t)FRAMES * 64];
__device__ float g_xg[(size_t)FRAMES * 256];
__device__ float g_lstm[(size_t)FRAMES * 64];
__device__ unsigned g_bfh[8 * BFRAG_PER_LAYER];   // weight B-fragments, hi part
__device__ unsigned g_bfl[8 * BFRAG_PER_LAYER];   // lo part

// ---------------- helpers ----------------
__device__ __forceinline__ unsigned pack_bf16(__nv_bfloat16 a, __nv_bfloat16 b) {
    return (unsigned)__bfloat16_as_ushort(a) | ((unsigned)__bfloat16_as_ushort(b) << 16);
}
__device__ __forceinline__ void mma_bf16(float* d, unsigned a0, unsigned a1,
                                         unsigned a2, unsigned a3,
                                         unsigned b0, unsigned b1) {
    asm volatile("mma.sync.aligned.m16n8k16.row.col.f32.bf16.bf16.f32 "
                 "{%0,%1,%2,%3},{%4,%5,%6,%7},{%8,%9},{%0,%1,%2,%3};\n"
                 : "+f"(d[0]), "+f"(d[1]), "+f"(d[2]), "+f"(d[3])
                 : "r"(a0), "r"(a1), "r"(a2), "r"(a3), "r"(b0), "r"(b1));
}
__device__ __forceinline__ float fast_sigmoid(float x) {
    return __fdividef(1.f, 1.f + __expf(-x));
}
__device__ __forceinline__ float fast_tanh(float x) {
    // tanh(x) = 1 - 2/(exp(2x)+1); __expf err ~1e-6 rel
    return 1.f - __fdividef(2.f, __expf(2.f * x) + 1.f);
}

// =====================================================================
// Kernel 0: repack conv weights into mma B-fragment layout, bf16 hi/lo.
// idx within layer = ((tap*4+ks)*8+n)*32 + lane ; 2 u32 regs each.
// b0 = {W[ic0],W[ic0+1]}, b1 = {W[ic0+8],W[ic0+9]}, ic0 = ks*16+2*(lane%4),
// oc = n*8 + lane/4.  Layer0: ic>=9 (and ks>0) are zero.
// =====================================================================
__global__ void bfrag_prep(const float* __restrict__ c0w, const float* __restrict__ cws)
{
    int t = blockIdx.x * 256 + threadIdx.x;
    if (t >= 8 * 9216) return;
    int lane = t & 31;
    int n    = (t >> 5) & 7;
    int ks   = (t >> 8) & 3;
    int tap  = (t >> 10) % 9;
    int L    = t / 9216;
    int oc   = n * 8 + (lane >> 2);
    int ic0  = ks * 16 + 2 * (lane & 3);

    float w[4];
#pragma unroll
    for (int e = 0; e < 4; ++e) {
        int ic = ic0 + (e >> 1) * 8 + (e & 1);
        float v = 0.f;
        if (L == 0) {
            if (ks == 0 && ic < 9) v = c0w[oc * 81 + ic * 9 + tap];
        } else {
            v = cws[(size_t)(L - 1) * 36864 + oc * 576 + ic * 9 + tap];
        }
        w[e] = v;
    }
    __nv_bfloat16 h[4], lo[4];
#pragma unroll
    for (int e = 0; e < 4; ++e) {
        h[e]  = __float2bfloat16(w[e]);
        lo[e] = __float2bfloat16(w[e] - __bfloat162float(h[e]));
    }
    size_t base = (size_t)t * 2;
    g_bfh[base]     = pack_bf16(h[0], h[1]);
    g_bfh[base + 1] = pack_bf16(h[2], h[3]);
    g_bfl[base]     = pack_bf16(lo[0], lo[1]);
    g_bfl[base + 1] = pack_bf16(lo[2], lo[3]);
}

// =====================================================================
// Kernel 1: fused 8-layer conv stack via mma.sync bf16x3, 1 CTA / frame.
// 9 warps = 9 M-tiles of 16 "padded output rows" (out_base = 13r+c).
// Each tap is a row-offset view of the padded pixel-major X plane.
// =====================================================================
__global__ __launch_bounds__(288, 1)
void conv_mma_kernel(const float* __restrict__ x,
                     const float* __restrict__ c0b, const float* __restrict__ cbs)
{
    extern __shared__ char smraw[];
    __nv_bfloat16* Xh = (__nv_bfloat16*)smraw;            // [172][72]
    __nv_bfloat16* Xl = Xh + XROWS * XSTRIDE;
    unsigned* Bsh = (unsigned*)(Xl + XROWS * XSTRIDE);    // 18432 u32
    unsigned* Bsl = Bsh + BFRAG_PER_LAYER;
    float* bias = (float*)(Bsl + BFRAG_PER_LAYER);        // 64 f32

    const int f    = blockIdx.x;
    const int tid  = threadIdx.x;
    const int warp = tid >> 5;    // M-tile 0..8
    const int lane = tid & 31;
    const int qid  = lane >> 2;   // row within fragment group
    const int tq   = lane & 3;

    // zero both X planes (2*172*72 bf16 == 172*72 u32)
    {
        unsigned* Xz = (unsigned*)Xh;
        for (int i = tid; i < XROWS * XSTRIDE; i += 288) Xz[i] = 0u;
    }
    __syncthreads();

    // load input frame: 9 channels into padded interior, split hi/lo
    const float* xf = x + (size_t)f * 9 * HW;
    for (int i = tid; i < 9 * HW; i += 288) {
        int ic = i / HW, pix = i % HW;
        int r = pix / 11, c = pix % 11;
        float v = xf[i];
        __nv_bfloat16 h = __float2bfloat16(v);
        __nv_bfloat16 l = __float2bfloat16(v - __bfloat162float(h));
        int row = 13 * r + c + 14;
        Xh[row * XSTRIDE + ic] = h;
        Xl[row * XSTRIDE + ic] = l;
    }
    float* gout = g_conv_out + (size_t)f * FCK;

    for (int L = 0; L < 8; ++L) {
        __syncthreads();  // X writes visible; previous layer's Bs reads done
        // stage this layer's B fragments (hi+lo, 147KB) into smem
        {
            const float4* sh = (const float4*)(g_bfh + L * BFRAG_PER_LAYER);
            const float4* sl = (const float4*)(g_bfl + L * BFRAG_PER_LAYER);
            float4* dh = (float4*)Bsh;
            float4* dl = (float4*)Bsl;
            for (int i = tid; i < BFRAG_PER_LAYER / 4; i += 288) {
                dh[i] = sh[i];
                dl[i] = sl[i];
            }
        }
        if (tid < 64) bias[tid] = (L == 0) ? c0b[tid] : cbs[(L - 1) * 64 + tid];
        __syncthreads();

        const int KS = (L == 0) ? 1 : 4;
        float acc[8][4];
#pragma unroll
        for (int n = 0; n < 8; ++n) {
            float b0 = bias[n * 8 + 2 * tq], b1 = bias[n * 8 + 2 * tq + 1];
            acc[n][0] = b0; acc[n][1] = b1; acc[n][2] = b0; acc[n][3] = b1;
        }

        for (int tap = 0; tap < 9; ++tap) {
            const int off = 13 * (tap / 3) + (tap % 3);
            const int r0 = 16 * warp + off + qid;
            for (int ks = 0; ks < KS; ++ks) {
                const int cb = ks * 16 + 2 * tq;  // element column
                const __nv_bfloat16* ph = Xh + r0 * XSTRIDE + cb;
                const __nv_bfloat16* pl = Xl + r0 * XSTRIDE + cb;
                unsigned ah0 = *(const unsigned*)(ph);
                unsigned ah1 = *(const unsigned*)(ph + 8 * XSTRIDE);
                unsigned ah2 = *(const unsigned*)(ph + 8);
                unsigned ah3 = *(const unsigned*)(ph + 8 * XSTRIDE + 8);
                unsigned al0 = *(const unsigned*)(pl);
                unsigned al1 = *(const unsigned*)(pl + 8 * XSTRIDE);
                unsigned al2 = *(const unsigned*)(pl + 8);
                unsigned al3 = *(const unsigned*)(pl + 8 * XSTRIDE + 8);

                const int base = ((tap * 4 + ks) * 8) * 64 + lane * 2;
#pragma unroll
                for (int n = 0; n < 8; ++n) {
                    uint2 bh = *(const uint2*)(Bsh + base + n * 64);
                    uint2 bl = *(const uint2*)(Bsl + base + n * 64);
                    mma_bf16(acc[n], ah0, ah1, ah2, ah3, bh.x, bh.y);
                    mma_bf16(acc[n], ah0, ah1, ah2, ah3, bl.x, bl.y);
                    mma_bf16(acc[n], al0, al1, al2, al3, bh.x, bh.y);
                }
            }
        }
        __syncthreads();  // all X reads of this layer complete

        // epilogue: relu, write back hi/lo (or fp32 to gmem for last layer)
#pragma unroll
        for (int n = 0; n < 8; ++n) {
            const int oc0 = n * 8 + 2 * tq;
#pragma unroll
            for (int half = 0; half < 2; ++half) {
                int ob = 16 * warp + qid + 8 * half;
                int cc = ob % 13, rr = ob / 13;
                if (ob <= 140 && cc <= 10) {
                    float v0 = fmaxf(acc[n][2 * half], 0.f);
                    float v1 = fmaxf(acc[n][2 * half + 1], 0.f);
                    if (L < 7) {
                        int row = ob + 14;
                        __nv_bfloat16 h0 = __float2bfloat16(v0);
                        __nv_bfloat16 h1 = __float2bfloat16(v1);
                        __nv_bfloat16 l0 = __float2bfloat16(v0 - __bfloat162float(h0));
                        __nv_bfloat16 l1 = __float2bfloat16(v1 - __bfloat162float(h1));
                        *(unsigned*)(Xh + row * XSTRIDE + oc0) = pack_bf16(h0, h1);
                        *(unsigned*)(Xl + row * XSTRIDE + oc0) = pack_bf16(l0, l1);
                    } else {
                        gout[oc0 * HW + rr * 11 + cc] = v0;
                        gout[(oc0 + 1) * HW + rr * 11 + cc] = v1;
                    }
                }
            }
        }
    }
}

// =====================================================================
// Kernel 2: FC GEMM  feats = relu(conv_out[4096,7744] @ fc_w^T + b)
// =====================================================================
__global__ __launch_bounds__(256)
void fc_kernel(const float* __restrict__ W, const float* __restrict__ b)
{
    __shared__ float As[64][33];
    __shared__ float Ws[64][33];
    const int m0 = blockIdx.x * 64;
    const int tid = threadIdx.x;
    const int tx = tid & 15, ty = tid >> 4;
    const float* A = g_conv_out;

    float acc[4][4] = {};
    for (int k0 = 0; k0 < FCK; k0 += 32) {
#pragma unroll
        for (int v = 0; v < 2; ++v) {
            int idx = tid + v * 256;
            int r = idx >> 3, c4 = (idx & 7) << 2;
            float4 a4 = *(const float4*)&A[(size_t)(m0 + r) * FCK + k0 + c4];
            As[r][c4] = a4.x; As[r][c4 + 1] = a4.y; As[r][c4 + 2] = a4.z; As[r][c4 + 3] = a4.w;
            float4 w4 = *(const float4*)&W[(size_t)r * FCK + k0 + c4];
            Ws[r][c4] = w4.x; Ws[r][c4 + 1] = w4.y; Ws[r][c4 + 2] = w4.z; Ws[r][c4 + 3] = w4.w;
        }
        __syncthreads();
#pragma unroll
        for (int kk = 0; kk < 32; ++kk) {
            float a[4], w[4];
#pragma unroll
            for (int i = 0; i < 4; ++i) a[i] = As[ty * 4 + i][kk];
#pragma unroll
            for (int j = 0; j < 4; ++j) w[j] = Ws[tx * 4 + j][kk];
#pragma unroll
            for (int i = 0; i < 4; ++i)
#pragma unroll
                for (int j = 0; j < 4; ++j) acc[i][j] = fmaf(a[i], w[j], acc[i][j]);
        }
        __syncthreads();
    }
#pragma unroll
    for (int i = 0; i < 4; ++i) {
        int m = m0 + ty * 4 + i;
#pragma unroll
        for (int j = 0; j < 4; ++j) {
            int n = tx * 4 + j;
            g_feats[(size_t)m * 64 + n] = fmaxf(acc[i][j] + b[n], 0.f);
        }
    }
}

// =====================================================================
// Kernel 3: xg = feats @ w_ih^T + b_ih + b_hh
// =====================================================================
__global__ __launch_bounds__(256)
void xgates_kernel(const float* __restrict__ w_ih,
                   const float* __restrict__ b_ih, const float* __restrict__ b_hh)
{
    __shared__ float fs[64][64];
    const int f0 = blockIdx.x * 64;
    const int g = threadIdx.x;
    float w[64];
#pragma unroll
    for (int k = 0; k < 64; ++k) w[k] = w_ih[g * 64 + k];
    for (int i = g; i < 64 * 64; i += 256) fs[i / 64][i % 64] = g_feats[(size_t)f0 * 64 + i];
    __syncthreads();
    const float bias = b_ih[g] + b_hh[g];
    for (int f = 0; f < 64; ++f) {
        float s = bias;
#pragma unroll
        for (int k = 0; k < 64; ++k) s = fmaf(w[k], fs[f][k], s);
        g_xg[(size_t)(f0 + f) * 256 + g] = s;
    }
}

// =====================================================================
// Kernel 4: recurrent LSTM, 32 CTAs (one per batch row)
// =====================================================================
__global__ __launch_bounds__(256)
void lstm_kernel(const float* __restrict__ w_hh)
{
    __shared__ float h_s[64];
    __shared__ float g_s[256];
    const int b = blockIdx.x;
    const int g = threadIdx.x;
    float w[64];
#pragma unroll
    for (int k = 0; k < 64; ++k) w[k] = w_hh[g * 64 + k];
    float c = 0.f;
    if (g < 64) h_s[g] = 0.f;
    __syncthreads();

    const float* xgb = g_xg + (size_t)b * 128 * 256;
    float* lob = g_lstm + (size_t)b * 128 * 64;
    for (int t = 0; t < 128; ++t) {
        float s = xgb[t * 256 + g];
#pragma unroll
        for (int k = 0; k < 64; ++k) s = fmaf(w[k], h_s[k], s);
        g_s[g] = s;
        __syncthreads();
        if (g < 64) {
            float ig = fast_sigmoid(g_s[g]);
            float fg = fast_sigmoid(g_s[64 + g]);
            float gg = fast_tanh(g_s[128 + g]);
            float og = fast_sigmoid(g_s[192 + g]);
            c = fg * c + ig * gg;
            float h = og * fast_tanh(c);
            lob[t * 64 + g] = h;
            h_s[g] = h;
        }
        __syncthreads();
    }
}

// =====================================================================
// Kernel 5: fused policy/value heads
// =====================================================================
__global__ __launch_bounds__(256)
void heads_kernel(const float* __restrict__ p1w, const float* __restrict__ p1b,
                  const float* __restrict__ p2w, const float* __restrict__ p2b,
                  const float* __restrict__ v1w, const float* __restrict__ v1b,
                  const float* __restrict__ v2w, const float* __restrict__ v2b,
                  float* __restrict__ out)
{
    __shared__ float h_s[32][64];
    __shared__ float p2s[6 * 128];
    __shared__ float v2s[128];
    __shared__ float u_s[256];

    const int f0 = blockIdx.x * 32;
    const int t = threadIdx.x;

    const float* wsrc = (t < 128) ? (p1w + t * 64) : (v1w + (t - 128) * 64);
    float w[64];
#pragma unroll
    for (int k = 0; k < 64; ++k) w[k] = wsrc[k];
    const float bias = (t < 128) ? p1b[t] : v1b[t - 128];

    for (int i = t; i < 32 * 64; i += 256) h_s[i / 64][i % 64] = g_lstm[(size_t)f0 * 64 + i];
    for (int i = t; i < 768; i += 256) p2s[i] = p2w[i];
    if (t < 128) v2s[t] = v2w[t];
    __syncthreads();

    const int warp = t >> 5, lane = t & 31;
    for (int fi = 0; fi < 32; ++fi) {
        float s = bias;
#pragma unroll
        for (int k = 0; k < 64; ++k) s = fmaf(w[k], h_s[fi][k], s);
        u_s[t] = fmaxf(s, 0.f);
        __syncthreads();

        const int f = f0 + fi;
        if (warp < 6) {
            float s2 = 0.f;
#pragma unroll
            for (int j = 0; j < 4; ++j)
                s2 = fmaf(p2s[warp * 128 + j * 32 + lane], u_s[j * 32 + lane], s2);
            for (int off = 16; off; off >>= 1) s2 += __shfl_down_sync(0xffffffffu, s2, off);
            if (lane == 0) out[f * 6 + warp] = s2 + p2b[warp];
        } else if (warp == 6) {
            float s2 = 0.f;
#pragma unroll
            for (int j = 0; j < 4; ++j)
                s2 = fmaf(v2s[j * 32 + lane], u_s[128 + j * 32 + lane], s2);
            for (int off = 16; off; off >>= 1) s2 += __shfl_down_sync(0xffffffffu, s2, off);
            if (lane == 0) out[FRAMES * 6 + f] = s2 + v2b[0];
        }
        __syncthreads();
    }
}

// =====================================================================
extern "C" void kernel_launch(void* const* d_in, const int* in_sizes, int n_in,
                              void* d_out, int out_size)
{
    const float* x    = (const float*)d_in[0];
    const float* c0w  = (const float*)d_in[1];
    const float* c0b  = (const float*)d_in[2];
    const float* cws  = (const float*)d_in[3];
    const float* cbs  = (const float*)d_in[4];
    const float* fcw  = (const float*)d_in[5];
    const float* fcb  = (const float*)d_in[6];
    const float* wih  = (const float*)d_in[7];
    const float* whh  = (const float*)d_in[8];
    const float* bih  = (const float*)d_in[9];
    const float* bhh  = (const float*)d_in[10];
    const float* p1w  = (const float*)d_in[11];
    const float* p1b  = (const float*)d_in[12];
    const float* p2w  = (const float*)d_in[13];
    const float* p2b  = (const float*)d_in[14];
    const float* v1w  = (const float*)d_in[15];
    const float* v1b  = (const float*)d_in[16];
    const float* v2w  = (const float*)d_in[17];
    const float* v2b  = (const float*)d_in[18];
    float* out = (float*)d_out;

    // smem: X hi/lo (2*172*72*2B) + Bfrag hi/lo (2*18432*4B) + bias (256B)
    const int conv_smem = 2 * XROWS * XSTRIDE * 2 + 2 * BFRAG_PER_LAYER * 4 + 256;
    cudaFuncSetAttribute(conv_mma_kernel,
                         cudaFuncAttributeMaxDynamicSharedMemorySize, conv_smem);

    bfrag_prep<<<288, 256>>>(c0w, cws);
    conv_mma_kernel<<<FRAMES, 288, conv_smem>>>(x, c0b, cbs);
    fc_kernel<<<FRAMES / 64, 256>>>(fcw, fcb);
    xgates_kernel<<<FRAMES / 64, 256>>>(wih, bih, bhh);
    lstm_kernel<<<32, 256>>>(whh);
    heads_kernel<<<FRAMES / 32, 256>>>(p1w, p1b, p2w, p2b, v1w, v1b, v2w, v2b, out);
}

// round 5
// speedup vs baseline: 6.3248x; 2.3730x over previous
#include <cuda_runtime.h>
#include <cuda_fp16.h>
#include <math.h>
#include <stdint.h>

// ---------------- problem constants ----------------
#define FRAMES 4096      // B*T
#define HW     121
#define FCK    7744
#define XSTRIDE 72       // X row stride in fp16 elems -> 144B, conflict-free
#define XROWS   172      // 13x13=169 plane + overread pad
#define BFRAGS  9216     // uint2 fragments per layer: 9 taps*4 ks*8 n*32 lanes

// ---------------- global scratch ----------------
__device__ __half g_conv_out[(size_t)FRAMES * FCK];
__device__ float g_feats[(size_t)FRAMES * 64];
__device__ float g_xg[(size_t)FRAMES * 256];
__device__ float g_lstm[(size_t)FRAMES * 64];
__device__ uint2 g_bf[8 * BFRAGS];   // fp16 weight B-fragments per layer

// ---------------- helpers ----------------
__device__ __forceinline__ unsigned pack_half2(__half a, __half b) {
    return (unsigned)__half_as_ushort(a) | ((unsigned)__half_as_ushort(b) << 16);
}
__device__ __forceinline__ void mma_f16(float* d, unsigned a0, unsigned a1,
                                        unsigned a2, unsigned a3,
                                        unsigned b0, unsigned b1) {
    asm volatile("mma.sync.aligned.m16n8k16.row.col.f32.f16.f16.f32 "
                 "{%0,%1,%2,%3},{%4,%5,%6,%7},{%8,%9},{%0,%1,%2,%3};\n"
                 : "+f"(d[0]), "+f"(d[1]), "+f"(d[2]), "+f"(d[3])
                 : "r"(a0), "r"(a1), "r"(a2), "r"(a3), "r"(b0), "r"(b1));
}
__device__ __forceinline__ float fast_sigmoid(float x) {
    return __fdividef(1.f, 1.f + __expf(-x));
}
__device__ __forceinline__ float fast_tanh(float x) {
    return 1.f - __fdividef(2.f, __expf(2.f * x) + 1.f);
}

// =====================================================================
// Kernel 0: repack conv weights into mma B-fragment layout (fp16).
// fragment t = (((L*9+tap)*4+ks)*8+n)*32 + lane
// b0 = {W[ic0],W[ic0+1]}, b1 = {W[ic0+8],W[ic0+9]}, ic0 = ks*16+2*(lane&3),
// oc = n*8 + lane/4. Layer0: only ks==0, ic<9 nonzero.
// =====================================================================
__global__ void bfrag_prep(const float* __restrict__ c0w, const float* __restrict__ cws)
{
    int t = blockIdx.x * 256 + threadIdx.x;
    if (t >= 8 * BFRAGS) return;
    int lane = t & 31;
    int n    = (t >> 5) & 7;
    int ks   = (t >> 8) & 3;
    int tap  = (t >> 10) % 9;
    int L    = t / BFRAGS;
    int oc   = n * 8 + (lane >> 2);
    int ic0  = ks * 16 + 2 * (lane & 3);

    __half h[4];
#pragma unroll
    for (int e = 0; e < 4; ++e) {
        int ic = ic0 + (e >> 1) * 8 + (e & 1);
        float v = 0.f;
        if (L == 0) {
            if (ks == 0 && ic < 9) v = c0w[oc * 81 + ic * 9 + tap];
        } else {
            v = cws[(size_t)(L - 1) * 36864 + oc * 576 + ic * 9 + tap];
        }
        h[e] = __float2half(v);
    }
    g_bf[t] = make_uint2(pack_half2(h[0], h[1]), pack_half2(h[2], h[3]));
}

// =====================================================================
// Kernel 1: fused 8-layer conv stack via mma.sync fp16, 1 CTA / frame.
// 9 warps = 9 M-tiles of 16 padded output rows (out_base = 13r+c).
// Each conv tap is a row-offset view of the pixel-major X plane.
// smem: X fp16 [172][72] + B frags (9216 uint2) + bias -> ~99KB, 2 CTAs/SM.
// =====================================================================
__global__ __launch_bounds__(288, 2)
void conv_mma_kernel(const float* __restrict__ x,
                     const float* __restrict__ c0b, const float* __restrict__ cbs)
{
    extern __shared__ char smraw[];
    __half* Xh = (__half*)smraw;                        // [172][72]
    uint2* Bs  = (uint2*)(Xh + XROWS * XSTRIDE);        // 9216 uint2
    float* bias = (float*)(Bs + BFRAGS);                // 64 f32

    const int f    = blockIdx.x;
    const int tid  = threadIdx.x;
    const int warp = tid >> 5;    // M-tile 0..8
    const int lane = tid & 31;
    const int qid  = lane >> 2;   // row within fragment group
    const int tq   = lane & 3;

    // zero X plane (halo stays zero forever)
    {
        unsigned* Xz = (unsigned*)Xh;
        for (int i = tid; i < XROWS * XSTRIDE / 2; i += 288) Xz[i] = 0u;
    }
    __syncthreads();

    // load input frame: 9 channels into padded interior
    const float* xf = x + (size_t)f * 9 * HW;
    for (int i = tid; i < 9 * HW; i += 288) {
        int ic = i / HW, pix = i % HW;
        int row = 13 * (pix / 11) + (pix % 11) + 14;
        Xh[row * XSTRIDE + ic] = __float2half(xf[i]);
    }
    __half* gout = g_conv_out + (size_t)f * FCK;

    for (int L = 0; L < 8; ++L) {
        __syncthreads();  // X writes visible; previous layer's Bs reads done
        // stage this layer's B fragments (72KB) into smem
        {
            const uint4* src = (const uint4*)(g_bf + (size_t)L * BFRAGS);
            uint4* dst = (uint4*)Bs;
            for (int i = tid; i < BFRAGS / 2; i += 288) dst[i] = src[i];
        }
        if (tid < 64) bias[tid] = (L == 0) ? c0b[tid] : cbs[(L - 1) * 64 + tid];
        __syncthreads();

        const int KS = (L == 0) ? 1 : 4;
        float acc[8][4];
#pragma unroll
        for (int n = 0; n < 8; ++n) {
            float b0 = bias[n * 8 + 2 * tq], b1 = bias[n * 8 + 2 * tq + 1];
            acc[n][0] = b0; acc[n][1] = b1; acc[n][2] = b0; acc[n][3] = b1;
        }

        for (int tap = 0; tap < 9; ++tap) {
            const int off = 13 * (tap / 3) + (tap % 3);
            const int r0 = 16 * warp + off + qid;
            for (int ks = 0; ks < KS; ++ks) {
                const __half* ph = Xh + r0 * XSTRIDE + (ks * 16 + 2 * tq);
                unsigned a0 = *(const unsigned*)(ph);
                unsigned a1 = *(const unsigned*)(ph + 8 * XSTRIDE);
                unsigned a2 = *(const unsigned*)(ph + 8);
                unsigned a3 = *(const unsigned*)(ph + 8 * XSTRIDE + 8);

                const uint2* bp = Bs + ((tap * 4 + ks) * 8) * 32 + lane;
#pragma unroll
                for (int n = 0; n < 8; ++n) {
                    uint2 b = bp[n * 32];
                    mma_f16(acc[n], a0, a1, a2, a3, b.x, b.y);
                }
            }
        }
        __syncthreads();  // all X reads of this layer complete

        // epilogue: relu, write back fp16 (or to gmem for last layer)
#pragma unroll
        for (int n = 0; n < 8; ++n) {
            const int oc0 = n * 8 + 2 * tq;
#pragma unroll
            for (int half = 0; half < 2; ++half) {
                int ob = 16 * warp + qid + 8 * half;
                int cc = ob % 13, rr = ob / 13;
                if (ob <= 140 && cc <= 10) {
                    float v0 = fmaxf(acc[n][2 * half], 0.f);
                    float v1 = fmaxf(acc[n][2 * half + 1], 0.f);
                    __half h0 = __float2half(v0);
                    __half h1 = __float2half(v1);
                    if (L < 7) {
                        *(unsigned*)(Xh + (ob + 14) * XSTRIDE + oc0) = pack_half2(h0, h1);
                    } else {
                        gout[oc0 * HW + rr * 11 + cc] = h0;
                        gout[(oc0 + 1) * HW + rr * 11 + cc] = h1;
                    }
                }
            }
        }
    }
}

// =====================================================================
// Kernel 2: FC GEMM  feats = relu(conv_out[4096,7744](fp16) @ fc_w^T + b)
// =====================================================================
__global__ __launch_bounds__(256)
void fc_kernel(const float* __restrict__ W, const float* __restrict__ b)
{
    __shared__ float As[64][33];
    __shared__ float Ws[64][33];
    const int m0 = blockIdx.x * 64;
    const int tid = threadIdx.x;
    const int tx = tid & 15, ty = tid >> 4;
    const __half* A = g_conv_out;

    float acc[4][4] = {};
    for (int k0 = 0; k0 < FCK; k0 += 32) {
        // A: 64 rows x 32 halves; each thread loads 8 halves (uint4)
        {
            int r = tid >> 2, ch = (tid & 3) << 3;
            uint4 u = *(const uint4*)&A[(size_t)(m0 + r) * FCK + k0 + ch];
            const __half* hp = (const __half*)&u;
#pragma unroll
            for (int e = 0; e < 8; ++e) As[r][ch + e] = __half2float(hp[e]);
        }
#pragma unroll
        for (int v = 0; v < 2; ++v) {
            int idx = tid + v * 256;
            int r = idx >> 3, c4 = (idx & 7) << 2;
            float4 w4 = *(const float4*)&W[(size_t)r * FCK + k0 + c4];
            Ws[r][c4] = w4.x; Ws[r][c4 + 1] = w4.y; Ws[r][c4 + 2] = w4.z; Ws[r][c4 + 3] = w4.w;
        }
        __syncthreads();
#pragma unroll
        for (int kk = 0; kk < 32; ++kk) {
            float a[4], w[4];
#pragma unroll
            for (int i = 0; i < 4; ++i) a[i] = As[ty * 4 + i][kk];
#pragma unroll
            for (int j = 0; j < 4; ++j) w[j] = Ws[tx * 4 + j][kk];
#pragma unroll
            for (int i = 0; i < 4; ++i)
#pragma unroll
                for (int j = 0; j < 4; ++j) acc[i][j] = fmaf(a[i], w[j], acc[i][j]);
        }
        __syncthreads();
    }
#pragma unroll
    for (int i = 0; i < 4; ++i) {
        int m = m0 + ty * 4 + i;
#pragma unroll
        for (int j = 0; j < 4; ++j) {
            int n = tx * 4 + j;
            g_feats[(size_t)m * 64 + n] = fmaxf(acc[i][j] + b[n], 0.f);
        }
    }
}

// =====================================================================
// Kernel 3: xg = feats @ w_ih^T + b_ih + b_hh
// =====================================================================
__global__ __launch_bounds__(256)
void xgates_kernel(const float* __restrict__ w_ih,
                   const float* __restrict__ b_ih, const float* __restrict__ b_hh)
{
    __shared__ float fs[64][64];
    const int f0 = blockIdx.x * 64;
    const int g = threadIdx.x;
    float w[64];
#pragma unroll
    for (int k = 0; k < 64; ++k) w[k] = w_ih[g * 64 + k];
    for (int i = g; i < 64 * 64; i += 256) fs[i / 64][i % 64] = g_feats[(size_t)f0 * 64 + i];
    __syncthreads();
    const float bias = b_ih[g] + b_hh[g];
    for (int f = 0; f < 64; ++f) {
        float s = bias;
#pragma unroll
        for (int k = 0; k < 64; ++k) s = fmaf(w[k], fs[f][k], s);
        g_xg[(size_t)(f0 + f) * 256 + g] = s;
    }
}

// =====================================================================
// Kernel 4: recurrent LSTM, 32 CTAs (one per batch row)
// =====================================================================
__global__ __launch_bounds__(256)
void lstm_kernel(const float* __restrict__ w_hh)
{
    __shared__ float h_s[64];
    __shared__ float g_s[256];
    const int b = blockIdx.x;
    const int g = threadIdx.x;
    float w[64];
#pragma unroll
    for (int k = 0; k < 64; ++k) w[k] = w_hh[g * 64 + k];
    float c = 0.f;
    if (g < 64) h_s[g] = 0.f;
    __syncthreads();

    const float* xgb = g_xg + (size_t)b * 128 * 256;
    float* lob = g_lstm + (size_t)b * 128 * 64;
    for (int t = 0; t < 128; ++t) {
        float s = xgb[t * 256 + g];
#pragma unroll
        for (int k = 0; k < 64; ++k) s = fmaf(w[k], h_s[k], s);
        g_s[g] = s;
        __syncthreads();
        if (g < 64) {
            float ig = fast_sigmoid(g_s[g]);
            float fg = fast_sigmoid(g_s[64 + g]);
            float gg = fast_tanh(g_s[128 + g]);
            float og = fast_sigmoid(g_s[192 + g]);
            c = fg * c + ig * gg;
            float h = og * fast_tanh(c);
            lob[t * 64 + g] = h;
            h_s[g] = h;
        }
        __syncthreads();
    }
}

// =====================================================================
// Kernel 5: fused policy/value heads
// =====================================================================
__global__ __launch_bounds__(256)
void heads_kernel(const float* __restrict__ p1w, const float* __restrict__ p1b,
                  const float* __restrict__ p2w, const float* __restrict__ p2b,
                  const float* __restrict__ v1w, const float* __restrict__ v1b,
                  const float* __restrict__ v2w, const float* __restrict__ v2b,
                  float* __restrict__ out)
{
    __shared__ float h_s[32][64];
    __shared__ float p2s[6 * 128];
    __shared__ float v2s[128];
    __shared__ float u_s[256];

    const int f0 = blockIdx.x * 32;
    const int t = threadIdx.x;

    const float* wsrc = (t < 128) ? (p1w + t * 64) : (v1w + (t - 128) * 64);
    float w[64];
#pragma unroll
    for (int k = 0; k < 64; ++k) w[k] = wsrc[k];
    const float bias = (t < 128) ? p1b[t] : v1b[t - 128];

    for (int i = t; i < 32 * 64; i += 256) h_s[i / 64][i % 64] = g_lstm[(size_t)f0 * 64 + i];
    for (int i = t; i < 768; i += 256) p2s[i] = p2w[i];
    if (t < 128) v2s[t] = v2w[t];
    __syncthreads();

    const int warp = t >> 5, lane = t & 31;
    for (int fi = 0; fi < 32; ++fi) {
        float s = bias;
#pragma unroll
        for (int k = 0; k < 64; ++k) s = fmaf(w[k], h_s[fi][k], s);
        u_s[t] = fmaxf(s, 0.f);
        __syncthreads();

        const int f = f0 + fi;
        if (warp < 6) {
            float s2 = 0.f;
#pragma unroll
            for (int j = 0; j < 4; ++j)
                s2 = fmaf(p2s[warp * 128 + j * 32 + lane], u_s[j * 32 + lane], s2);
            for (int off = 16; off; off >>= 1) s2 += __shfl_down_sync(0xffffffffu, s2, off);
            if (lane == 0) out[f * 6 + warp] = s2 + p2b[warp];
        } else if (warp == 6) {
            float s2 = 0.f;
#pragma unroll
            for (int j = 0; j < 4; ++j)
                s2 = fmaf(v2s[j * 32 + lane], u_s[128 + j * 32 + lane], s2);
            for (int off = 16; off; off >>= 1) s2 += __shfl_down_sync(0xffffffffu, s2, off);
            if (lane == 0) out[FRAMES * 6 + f] = s2 + v2b[0];
        }
        __syncthreads();
    }
}

// =====================================================================
extern "C" void kernel_launch(void* const* d_in, const int* in_sizes, int n_in,
                              void* d_out, int out_size)
{
    const float* x    = (const float*)d_in[0];
    const float* c0w  = (const float*)d_in[1];
    const float* c0b  = (const float*)d_in[2];
    const float* cws  = (const float*)d_in[3];
    const float* cbs  = (const float*)d_in[4];
    const float* fcw  = (const float*)d_in[5];
    const float* fcb  = (const float*)d_in[6];
    const float* wih  = (const float*)d_in[7];
    const float* whh  = (const float*)d_in[8];
    const float* bih  = (const float*)d_in[9];
    const float* bhh  = (const float*)d_in[10];
    const float* p1w  = (const float*)d_in[11];
    const float* p1b  = (const float*)d_in[12];
    const float* p2w  = (const float*)d_in[13];
    const float* p2b  = (const float*)d_in[14];
    const float* v1w  = (const float*)d_in[15];
    const float* v1b  = (const float*)d_in[16];
    const float* v2w  = (const float*)d_in[17];
    const float* v2b  = (const float*)d_in[18];
    float* out = (float*)d_out;

    // smem: X (172*72*2B) + Bfrag (9216*8B) + bias (256B) = 98,752 B
    const int conv_smem = XROWS * XSTRIDE * 2 + BFRAGS * 8 + 256;
    cudaFuncSetAttribute(conv_mma_kernel,
                         cudaFuncAttributeMaxDynamicSharedMemorySize, conv_smem);

    bfrag_prep<<<288, 256>>>(c0w, cws);
    conv_mma_kernel<<<FRAMES, 288, conv_smem>>>(x, c0b, cbs);
    fc_kernel<<<FRAMES / 64, 256>>>(fcw, fcb);
    xgates_kernel<<<FRAMES / 64, 256>>>(wih, bih, bhh);
    lstm_kernel<<<32, 256>>>(whh);
    heads_kernel<<<FRAMES / 32, 256>>>(p1w, p1b, p2w, p2b, v1w, v1b, v2w, v2b, out);
}

// round 6
// speedup vs baseline: 7.1820x; 1.1355x over previous
#include <cuda_runtime.h>
#include <cuda_fp16.h>
#include <math.h>
#include <stdint.h>

// ---------------- problem constants ----------------
#define FRAMES 4096      // B*T
#define HW     121
#define FCK    7744
#define XSTRIDE 72       // X row stride in fp16 elems -> 144B, conflict-free
#define XROWS   172      // 13x13=169 plane + overread pad
#define BFRAGS  9216     // uint2 fragments per layer: 9 taps*4 ks*8 n*32 lanes
#define FC_KS   484      // 7744/16

// ---------------- global scratch ----------------
__device__ __half g_conv_out[(size_t)FRAMES * FCK];
__device__ float g_feats[(size_t)FRAMES * 64];
__device__ float g_xg[(size_t)FRAMES * 256];
__device__ float g_lstm[(size_t)FRAMES * 64];
__device__ uint2 g_bf[8 * BFRAGS];            // conv weight B-fragments (fp16)
__device__ uint4 g_wfc[FC_KS * 8 * 32];       // FC weight frags: hi(x,y) lo(z,w)

// ---------------- helpers ----------------
__device__ __forceinline__ unsigned pack_half2(__half a, __half b) {
    return (unsigned)__half_as_ushort(a) | ((unsigned)__half_as_ushort(b) << 16);
}
__device__ __forceinline__ void mma_f16(float* d, unsigned a0, unsigned a1,
                                        unsigned a2, unsigned a3,
                                        unsigned b0, unsigned b1) {
    asm volatile("mma.sync.aligned.m16n8k16.row.col.f32.f16.f16.f32 "
                 "{%0,%1,%2,%3},{%4,%5,%6,%7},{%8,%9},{%0,%1,%2,%3};\n"
                 : "+f"(d[0]), "+f"(d[1]), "+f"(d[2]), "+f"(d[3])
                 : "r"(a0), "r"(a1), "r"(a2), "r"(a3), "r"(b0), "r"(b1));
}
__device__ __forceinline__ float fast_sigmoid(float x) {
    return __fdividef(1.f, 1.f + __expf(-x));
}
__device__ __forceinline__ float fast_tanh(float x) {
    return 1.f - __fdividef(2.f, __expf(2.f * x) + 1.f);
}

// =====================================================================
// Kernel 0a: conv weights -> mma B-fragments (fp16)
// =====================================================================
__global__ void bfrag_prep(const float* __restrict__ c0w, const float* __restrict__ cws)
{
    int t = blockIdx.x * 256 + threadIdx.x;
    if (t >= 8 * BFRAGS) return;
    int lane = t & 31;
    int n    = (t >> 5) & 7;
    int ks   = (t >> 8) & 3;
    int tap  = (t >> 10) % 9;
    int L    = t / BFRAGS;
    int oc   = n * 8 + (lane >> 2);
    int ic0  = ks * 16 + 2 * (lane & 3);

    __half h[4];
#pragma unroll
    for (int e = 0; e < 4; ++e) {
        int ic = ic0 + (e >> 1) * 8 + (e & 1);
        float v = 0.f;
        if (L == 0) {
            if (ks == 0 && ic < 9) v = c0w[oc * 81 + ic * 9 + tap];
        } else {
            v = cws[(size_t)(L - 1) * 36864 + oc * 576 + ic * 9 + tap];
        }
        h[e] = __float2half(v);
    }
    g_bf[t] = make_uint2(pack_half2(h[0], h[1]), pack_half2(h[2], h[3]));
}

// =====================================================================
// Kernel 0b: FC weights -> mma B-fragments, hi/lo fp16 split (lossless-ish)
// t = (ks*8 + n)*32 + lane ; k = ks*16 + 2*(lane&3) + {0,1,8,9} ; oc = n*8+lane/4
// =====================================================================
__global__ void wfrag_prep(const float* __restrict__ fcw)
{
    int t = blockIdx.x * 256 + threadIdx.x;
    if (t >= FC_KS * 8 * 32) return;
    int lane = t & 31;
    int n    = (t >> 5) & 7;
    int ks   = t >> 8;
    int oc   = n * 8 + (lane >> 2);
    int k0   = ks * 16 + 2 * (lane & 3);

    __half h[4], lo[4];
#pragma unroll
    for (int e = 0; e < 4; ++e) {
        int k = k0 + (e >> 1) * 8 + (e & 1);
        float v = fcw[(size_t)oc * FCK + k];
        h[e]  = __float2half(v);
        lo[e] = __float2half(v - __half2float(h[e]));
    }
    g_wfc[t] = make_uint4(pack_half2(h[0], h[1]), pack_half2(h[2], h[3]),
                          pack_half2(lo[0], lo[1]), pack_half2(lo[2], lo[3]));
}

// =====================================================================
// Kernel 1: fused 8-layer conv stack via mma.sync fp16, 1 CTA / frame.
// (unchanged from round 5 — measured at the fallback-HMMA roofline)
// =====================================================================
__global__ __launch_bounds__(288, 2)
void conv_mma_kernel(const float* __restrict__ x,
                     const float* __restrict__ c0b, const float* __restrict__ cbs)
{
    extern __shared__ char smraw[];
    __half* Xh = (__half*)smraw;                        // [172][72]
    uint2* Bs  = (uint2*)(Xh + XROWS * XSTRIDE);        // 9216 uint2
    float* bias = (float*)(Bs + BFRAGS);                // 64 f32

    const int f    = blockIdx.x;
    const int tid  = threadIdx.x;
    const int warp = tid >> 5;
    const int lane = tid & 31;
    const int qid  = lane >> 2;
    const int tq   = lane & 3;

    {
        unsigned* Xz = (unsigned*)Xh;
        for (int i = tid; i < XROWS * XSTRIDE / 2; i += 288) Xz[i] = 0u;
    }
    __syncthreads();

    const float* xf = x + (size_t)f * 9 * HW;
    for (int i = tid; i < 9 * HW; i += 288) {
        int ic = i / HW, pix = i % HW;
        int row = 13 * (pix / 11) + (pix % 11) + 14;
        Xh[row * XSTRIDE + ic] = __float2half(xf[i]);
    }
    __half* gout = g_conv_out + (size_t)f * FCK;

    for (int L = 0; L < 8; ++L) {
        __syncthreads();
        {
            const uint4* src = (const uint4*)(g_bf + (size_t)L * BFRAGS);
            uint4* dst = (uint4*)Bs;
            for (int i = tid; i < BFRAGS / 2; i += 288) dst[i] = src[i];
        }
        if (tid < 64) bias[tid] = (L == 0) ? c0b[tid] : cbs[(L - 1) * 64 + tid];
        __syncthreads();

        const int KS = (L == 0) ? 1 : 4;
        float acc[8][4];
#pragma unroll
        for (int n = 0; n < 8; ++n) {
            float b0 = bias[n * 8 + 2 * tq], b1 = bias[n * 8 + 2 * tq + 1];
            acc[n][0] = b0; acc[n][1] = b1; acc[n][2] = b0; acc[n][3] = b1;
        }

        for (int tap = 0; tap < 9; ++tap) {
            const int off = 13 * (tap / 3) + (tap % 3);
            const int r0 = 16 * warp + off + qid;
            for (int ks = 0; ks < KS; ++ks) {
                const __half* ph = Xh + r0 * XSTRIDE + (ks * 16 + 2 * tq);
                unsigned a0 = *(const unsigned*)(ph);
                unsigned a1 = *(const unsigned*)(ph + 8 * XSTRIDE);
                unsigned a2 = *(const unsigned*)(ph + 8);
                unsigned a3 = *(const unsigned*)(ph + 8 * XSTRIDE + 8);

                const uint2* bp = Bs + ((tap * 4 + ks) * 8) * 32 + lane;
#pragma unroll
                for (int n = 0; n < 8; ++n) {
                    uint2 b = bp[n * 32];
                    mma_f16(acc[n], a0, a1, a2, a3, b.x, b.y);
                }
            }
        }
        __syncthreads();

#pragma unroll
        for (int n = 0; n < 8; ++n) {
            const int oc0 = n * 8 + 2 * tq;
#pragma unroll
            for (int half = 0; half < 2; ++half) {
                int ob = 16 * warp + qid + 8 * half;
                int cc = ob % 13, rr = ob / 13;
                if (ob <= 140 && cc <= 10) {
                    float v0 = fmaxf(acc[n][2 * half], 0.f);
                    float v1 = fmaxf(acc[n][2 * half + 1], 0.f);
                    __half h0 = __float2half(v0);
                    __half h1 = __float2half(v1);
                    if (L < 7) {
                        *(unsigned*)(Xh + (ob + 14) * XSTRIDE + oc0) = pack_half2(h0, h1);
                    } else {
                        gout[oc0 * HW + rr * 11 + cc] = h0;
                        gout[(oc0 + 1) * HW + rr * 11 + cc] = h1;
                    }
                }
            }
        }
    }
}

// =====================================================================
// Kernel 2: FC GEMM on mma fp16 (W hi/lo). 128 CTAs x M=32, N=64, K=7744.
// 8 warps: warp = mt*4 + nq; mt in {0,1} (M-tile 16), nq -> n in {2nq, 2nq+1}.
// =====================================================================
__global__ __launch_bounds__(256)
void fc_mma_kernel(const float* __restrict__ b)
{
    __shared__ __half As[32][40];      // padded stride 40 halves = 80B
    __shared__ uint4 Bs[512];          // 2 ks * 8 n * 32 lanes

    const int m0 = blockIdx.x * 32;
    const int tid = threadIdx.x;
    const int warp = tid >> 5, lane = tid & 31;
    const int mt = warp >> 2, nq = warp & 3;
    const int qid = lane >> 2, tq = lane & 3;

    float acc[2][4] = {};

    for (int ci = 0; ci < FC_KS / 2; ++ci) {
        const int k0 = ci * 32;
        // stage A: 32 rows x 32 halves (threads 0..127, one uint4 each)
        if (tid < 128) {
            int r = tid >> 2, q = tid & 3;
            uint4 u = *(const uint4*)&g_conv_out[(size_t)(m0 + r) * FCK + k0 + q * 8];
            *(uint4*)&As[r][q * 8] = u;
        }
        // stage B frags: 512 uint4
        {
            const uint4* src = g_wfc + (size_t)ci * 512;
            Bs[tid] = src[tid];
            Bs[tid + 256] = src[tid + 256];
        }
        __syncthreads();

#pragma unroll
        for (int ks2 = 0; ks2 < 2; ++ks2) {
            const int r0 = mt * 16 + qid;
            const int cb = ks2 * 16 + 2 * tq;
            unsigned a0 = *(const unsigned*)&As[r0][cb];
            unsigned a1 = *(const unsigned*)&As[r0 + 8][cb];
            unsigned a2 = *(const unsigned*)&As[r0][cb + 8];
            unsigned a3 = *(const unsigned*)&As[r0 + 8][cb + 8];
#pragma unroll
            for (int j = 0; j < 2; ++j) {
                int n = nq * 2 + j;
                uint4 bb = Bs[(ks2 * 8 + n) * 32 + lane];
                mma_f16(acc[j], a0, a1, a2, a3, bb.x, bb.y);
                mma_f16(acc[j], a0, a1, a2, a3, bb.z, bb.w);
            }
        }
        __syncthreads();
    }

    // epilogue: bias + relu
#pragma unroll
    for (int j = 0; j < 2; ++j) {
        const int col = (nq * 2 + j) * 8 + 2 * tq;
        const float b0 = b[col], b1 = b[col + 1];
#pragma unroll
        for (int half = 0; half < 2; ++half) {
            int m = m0 + mt * 16 + qid + 8 * half;
            g_feats[(size_t)m * 64 + col]     = fmaxf(acc[j][2 * half] + b0, 0.f);
            g_feats[(size_t)m * 64 + col + 1] = fmaxf(acc[j][2 * half + 1] + b1, 0.f);
        }
    }
}

// =====================================================================
// Kernel 3: xg = feats @ w_ih^T + b_ih + b_hh
// =====================================================================
__global__ __launch_bounds__(256)
void xgates_kernel(const float* __restrict__ w_ih,
                   const float* __restrict__ b_ih, const float* __restrict__ b_hh)
{
    __shared__ float fs[64][64];
    const int f0 = blockIdx.x * 64;
    const int g = threadIdx.x;
    float w[64];
#pragma unroll
    for (int k = 0; k < 64; ++k) w[k] = w_ih[g * 64 + k];
    for (int i = g; i < 64 * 64; i += 256) fs[i / 64][i % 64] = g_feats[(size_t)f0 * 64 + i];
    __syncthreads();
    const float bias = b_ih[g] + b_hh[g];
    for (int f = 0; f < 64; ++f) {
        float s = bias;
#pragma unroll
        for (int k = 0; k < 64; ++k) s = fmaf(w[k], fs[f][k], s);
        g_xg[(size_t)(f0 + f) * 256 + g] = s;
    }
}

// =====================================================================
// Kernel 4: recurrent LSTM. 32 CTAs, 512 threads; gate dot split over 2 lanes.
// =====================================================================
__global__ __launch_bounds__(512)
void lstm_kernel(const float* __restrict__ w_hh)
{
    __shared__ float h_s[64];
    __shared__ float g_s[256];
    const int b = blockIdx.x;
    const int tid = threadIdx.x;
    const int g = tid >> 1, hh = tid & 1;

    float w[32];
#pragma unroll
    for (int k = 0; k < 32; ++k) w[k] = w_hh[g * 64 + hh * 32 + k];
    float c = 0.f;
    if (tid < 64) h_s[tid] = 0.f;
    __syncthreads();

    const float* xgb = g_xg + (size_t)b * 128 * 256;
    float* lob = g_lstm + (size_t)b * 128 * 64;

    float xnext = (hh == 0) ? xgb[g] : 0.f;
    for (int t = 0; t < 128; ++t) {
        float s1 = 0.f, s2 = 0.f;
        const float* hp = h_s + hh * 32;
#pragma unroll
        for (int k = 0; k < 16; ++k) {
            s1 = fmaf(w[k], hp[k], s1);
            s2 = fmaf(w[k + 16], hp[k + 16], s2);
        }
        float s = xnext + s1 + s2;
        s += __shfl_xor_sync(0xffffffffu, s, 1);
        if (hh == 0) {
            g_s[g] = s;
            if (t < 127) xnext = xgb[(t + 1) * 256 + g];
        }
        __syncthreads();
        if (tid < 64) {
            float ig = fast_sigmoid(g_s[tid]);
            float fg = fast_sigmoid(g_s[64 + tid]);
            float gg = fast_tanh(g_s[128 + tid]);
            float og = fast_sigmoid(g_s[192 + tid]);
            c = fg * c + ig * gg;
            float h = og * fast_tanh(c);
            lob[t * 64 + tid] = h;
            h_s[tid] = h;
        }
        __syncthreads();
    }
}

// =====================================================================
// Kernel 5: fused policy/value heads
// =====================================================================
__global__ __launch_bounds__(256)
void heads_kernel(const float* __restrict__ p1w, const float* __restrict__ p1b,
                  const float* __restrict__ p2w, const float* __restrict__ p2b,
                  const float* __restrict__ v1w, const float* __restrict__ v1b,
                  const float* __restrict__ v2w, const float* __restrict__ v2b,
                  float* __restrict__ out)
{
    __shared__ float h_s[32][64];
    __shared__ float p2s[6 * 128];
    __shared__ float v2s[128];
    __shared__ float u_s[256];

    const int f0 = blockIdx.x * 32;
    const int t = threadIdx.x;

    const float* wsrc = (t < 128) ? (p1w + t * 64) : (v1w + (t - 128) * 64);
    float w[64];
#pragma unroll
    for (int k = 0; k < 64; ++k) w[k] = wsrc[k];
    const float bias = (t < 128) ? p1b[t] : v1b[t - 128];

    for (int i = t; i < 32 * 64; i += 256) h_s[i / 64][i % 64] = g_lstm[(size_t)f0 * 64 + i];
    for (int i = t; i < 768; i += 256) p2s[i] = p2w[i];
    if (t < 128) v2s[t] = v2w[t];
    __syncthreads();

    const int warp = t >> 5, lane = t & 31;
    for (int fi = 0; fi < 32; ++fi) {
        float s = bias;
#pragma unroll
        for (int k = 0; k < 64; ++k) s = fmaf(w[k], h_s[fi][k], s);
        u_s[t] = fmaxf(s, 0.f);
        __syncthreads();

        const int f = f0 + fi;
        if (warp < 6) {
            float s2 = 0.f;
#pragma unroll
            for (int j = 0; j < 4; ++j)
                s2 = fmaf(p2s[warp * 128 + j * 32 + lane], u_s[j * 32 + lane], s2);
            for (int off = 16; off; off >>= 1) s2 += __shfl_down_sync(0xffffffffu, s2, off);
            if (lane == 0) out[f * 6 + warp] = s2 + p2b[warp];
        } else if (warp == 6) {
            float s2 = 0.f;
#pragma unroll
            for (int j = 0; j < 4; ++j)
                s2 = fmaf(v2s[j * 32 + lane], u_s[128 + j * 32 + lane], s2);
            for (int off = 16; off; off >>= 1) s2 += __shfl_down_sync(0xffffffffu, s2, off);
            if (lane == 0) out[FRAMES * 6 + f] = s2 + v2b[0];
        }
        __syncthreads();
    }
}

// =====================================================================
extern "C" void kernel_launch(void* const* d_in, const int* in_sizes, int n_in,
                              void* d_out, int out_size)
{
    const float* x    = (const float*)d_in[0];
    const float* c0w  = (const float*)d_in[1];
    const float* c0b  = (const float*)d_in[2];
    const float* cws  = (const float*)d_in[3];
    const float* cbs  = (const float*)d_in[4];
    const float* fcw  = (const float*)d_in[5];
    const float* fcb  = (const float*)d_in[6];
    const float* wih  = (const float*)d_in[7];
    const float* whh  = (const float*)d_in[8];
    const float* bih  = (const float*)d_in[9];
    const float* bhh  = (const float*)d_in[10];
    const float* p1w  = (const float*)d_in[11];
    const float* p1b  = (const float*)d_in[12];
    const float* p2w  = (const float*)d_in[13];
    const float* p2b  = (const float*)d_in[14];
    const float* v1w  = (const float*)d_in[15];
    const float* v1b  = (const float*)d_in[16];
    const float* v2w  = (const float*)d_in[17];
    const float* v2b  = (const float*)d_in[18];
    float* out = (float*)d_out;

    const int conv_smem = XROWS * XSTRIDE * 2 + BFRAGS * 8 + 256;
    cudaFuncSetAttribute(conv_mma_kernel,
                         cudaFuncAttributeMaxDynamicSharedMemorySize, conv_smem);

    bfrag_prep<<<288, 256>>>(c0w, cws);
    wfrag_prep<<<(FC_KS * 8 * 32 + 255) / 256, 256>>>(fcw);
    conv_mma_kernel<<<FRAMES, 288, conv_smem>>>(x, c0b, cbs);
    fc_mma_kernel<<<FRAMES / 32, 256>>>(fcb);
    xgates_kernel<<<FRAMES / 64, 256>>>(wih, bih, bhh);
    lstm_kernel<<<32, 512>>>(whh);
    heads_kernel<<<FRAMES / 32, 256>>>(p1w, p1b, p2w, p2b, v1w, v1b, v2w, v2b, out);
}

// round 7
// speedup vs baseline: 7.6076x; 1.0593x over previous
#include <cuda_runtime.h>
#include <cuda_fp16.h>
#include <math.h>
#include <stdint.h>

// ---------------- problem constants ----------------
#define FRAMES 4096      // B*T
#define HW     121
#define FCK    7744
#define XSTRIDE 72       // X row stride in fp16 elems -> 144B, conflict-free
#define XROWS   172      // 13x13=169 plane + overread pad
#define BFRAGS  9216     // uint2 fragments per layer: 9 taps*4 ks*8 n*32 lanes
#define FC_KS   484      // 7744/16
#define FC_SPLITS 4
#define FC_KS_PER 121    // 484/4

// ---------------- global scratch ----------------
__device__ __half g_conv_out[(size_t)FRAMES * FCK];
__device__ float g_fc_part[(size_t)FC_SPLITS * FRAMES * 64];
__device__ float g_xg[(size_t)FRAMES * 256];
__device__ float g_lstm[(size_t)FRAMES * 64];
__device__ uint2 g_bf[8 * BFRAGS];            // conv weight B-fragments (fp16)
__device__ uint4 g_wfc[FC_KS * 8 * 32];       // FC weight frags: hi(x,y) lo(z,w)

// ---------------- helpers ----------------
__device__ __forceinline__ unsigned pack_half2(__half a, __half b) {
    return (unsigned)__half_as_ushort(a) | ((unsigned)__half_as_ushort(b) << 16);
}
__device__ __forceinline__ void mma_f16(float* d, unsigned a0, unsigned a1,
                                        unsigned a2, unsigned a3,
                                        unsigned b0, unsigned b1) {
    asm volatile("mma.sync.aligned.m16n8k16.row.col.f32.f16.f16.f32 "
                 "{%0,%1,%2,%3},{%4,%5,%6,%7},{%8,%9},{%0,%1,%2,%3};\n"
                 : "+f"(d[0]), "+f"(d[1]), "+f"(d[2]), "+f"(d[3])
                 : "r"(a0), "r"(a1), "r"(a2), "r"(a3), "r"(b0), "r"(b1));
}
__device__ __forceinline__ float fast_sigmoid(float x) {
    return __fdividef(1.f, 1.f + __expf(-x));
}
__device__ __forceinline__ float fast_tanh(float x) {
    return 1.f - __fdividef(2.f, __expf(2.f * x) + 1.f);
}

// =====================================================================
// Kernel 0a: conv weights -> mma B-fragments (fp16)
// =====================================================================
__global__ void bfrag_prep(const float* __restrict__ c0w, const float* __restrict__ cws)
{
    int t = blockIdx.x * 256 + threadIdx.x;
    if (t >= 8 * BFRAGS) return;
    int lane = t & 31;
    int n    = (t >> 5) & 7;
    int ks   = (t >> 8) & 3;
    int tap  = (t >> 10) % 9;
    int L    = t / BFRAGS;
    int oc   = n * 8 + (lane >> 2);
    int ic0  = ks * 16 + 2 * (lane & 3);

    __half h[4];
#pragma unroll
    for (int e = 0; e < 4; ++e) {
        int ic = ic0 + (e >> 1) * 8 + (e & 1);
        float v = 0.f;
        if (L == 0) {
            if (ks == 0 && ic < 9) v = c0w[oc * 81 + ic * 9 + tap];
        } else {
            v = cws[(size_t)(L - 1) * 36864 + oc * 576 + ic * 9 + tap];
        }
        h[e] = __float2half(v);
    }
    g_bf[t] = make_uint2(pack_half2(h[0], h[1]), pack_half2(h[2], h[3]));
}

// =====================================================================
// Kernel 0b: FC weights -> mma B-fragments, hi/lo fp16 split
// =====================================================================
__global__ void wfrag_prep(const float* __restrict__ fcw)
{
    int t = blockIdx.x * 256 + threadIdx.x;
    if (t >= FC_KS * 8 * 32) return;
    int lane = t & 31;
    int n    = (t >> 5) & 7;
    int ks   = t >> 8;
    int oc   = n * 8 + (lane >> 2);
    int k0   = ks * 16 + 2 * (lane & 3);

    __half h[4], lo[4];
#pragma unroll
    for (int e = 0; e < 4; ++e) {
        int k = k0 + (e >> 1) * 8 + (e & 1);
        float v = fcw[(size_t)oc * FCK + k];
        h[e]  = __float2half(v);
        lo[e] = __float2half(v - __half2float(h[e]));
    }
    g_wfc[t] = make_uint4(pack_half2(h[0], h[1]), pack_half2(h[2], h[3]),
                          pack_half2(lo[0], lo[1]), pack_half2(lo[2], lo[3]));
}

// =====================================================================
// Kernel 1: fused 8-layer conv stack via mma.sync fp16, 1 CTA / frame.
// (at the fallback-HMMA roofline — unchanged)
// =====================================================================
__global__ __launch_bounds__(288, 2)
void conv_mma_kernel(const float* __restrict__ x,
                     const float* __restrict__ c0b, const float* __restrict__ cbs)
{
    extern __shared__ char smraw[];
    __half* Xh = (__half*)smraw;                        // [172][72]
    uint2* Bs  = (uint2*)(Xh + XROWS * XSTRIDE);        // 9216 uint2
    float* bias = (float*)(Bs + BFRAGS);                // 64 f32

    const int f    = blockIdx.x;
    const int tid  = threadIdx.x;
    const int warp = tid >> 5;
    const int lane = tid & 31;
    const int qid  = lane >> 2;
    const int tq   = lane & 3;

    {
        unsigned* Xz = (unsigned*)Xh;
        for (int i = tid; i < XROWS * XSTRIDE / 2; i += 288) Xz[i] = 0u;
    }
    __syncthreads();

    const float* xf = x + (size_t)f * 9 * HW;
    for (int i = tid; i < 9 * HW; i += 288) {
        int ic = i / HW, pix = i % HW;
        int row = 13 * (pix / 11) + (pix % 11) + 14;
        Xh[row * XSTRIDE + ic] = __float2half(xf[i]);
    }
    __half* gout = g_conv_out + (size_t)f * FCK;

    for (int L = 0; L < 8; ++L) {
        __syncthreads();
        {
            const uint4* src = (const uint4*)(g_bf + (size_t)L * BFRAGS);
            uint4* dst = (uint4*)Bs;
            for (int i = tid; i < BFRAGS / 2; i += 288) dst[i] = src[i];
        }
        if (tid < 64) bias[tid] = (L == 0) ? c0b[tid] : cbs[(L - 1) * 64 + tid];
        __syncthreads();

        const int KS = (L == 0) ? 1 : 4;
        float acc[8][4];
#pragma unroll
        for (int n = 0; n < 8; ++n) {
            float b0 = bias[n * 8 + 2 * tq], b1 = bias[n * 8 + 2 * tq + 1];
            acc[n][0] = b0; acc[n][1] = b1; acc[n][2] = b0; acc[n][3] = b1;
        }

        for (int tap = 0; tap < 9; ++tap) {
            const int off = 13 * (tap / 3) + (tap % 3);
            const int r0 = 16 * warp + off + qid;
            for (int ks = 0; ks < KS; ++ks) {
                const __half* ph = Xh + r0 * XSTRIDE + (ks * 16 + 2 * tq);
                unsigned a0 = *(const unsigned*)(ph);
                unsigned a1 = *(const unsigned*)(ph + 8 * XSTRIDE);
                unsigned a2 = *(const unsigned*)(ph + 8);
                unsigned a3 = *(const unsigned*)(ph + 8 * XSTRIDE + 8);

                const uint2* bp = Bs + ((tap * 4 + ks) * 8) * 32 + lane;
#pragma unroll
                for (int n = 0; n < 8; ++n) {
                    uint2 b = bp[n * 32];
                    mma_f16(acc[n], a0, a1, a2, a3, b.x, b.y);
                }
            }
        }
        __syncthreads();

#pragma unroll
        for (int n = 0; n < 8; ++n) {
            const int oc0 = n * 8 + 2 * tq;
#pragma unroll
            for (int half = 0; half < 2; ++half) {
                int ob = 16 * warp + qid + 8 * half;
                int cc = ob % 13, rr = ob / 13;
                if (ob <= 140 && cc <= 10) {
                    float v0 = fmaxf(acc[n][2 * half], 0.f);
                    float v1 = fmaxf(acc[n][2 * half + 1], 0.f);
                    __half h0 = __float2half(v0);
                    __half h1 = __float2half(v1);
                    if (L < 7) {
                        *(unsigned*)(Xh + (ob + 14) * XSTRIDE + oc0) = pack_half2(h0, h1);
                    } else {
                        gout[oc0 * HW + rr * 11 + cc] = h0;
                        gout[(oc0 + 1) * HW + rr * 11 + cc] = h1;
                    }
                }
            }
        }
    }
}

// =====================================================================
// Kernel 2: FC GEMM, split-K x4, double-buffered.
// grid (128, 4): x = M-tile of 32 rows, y = K-split (121 ks-chunks of 16).
// 8 warps: mt = warp>>2 (M 16-tile), nq = warp&3 (2 n-cols of 8).
// Writes fp32 partials (no bias/relu) to g_fc_part[split].
// =====================================================================
__global__ __launch_bounds__(256)
void fc_mma_kernel()
{
    __shared__ __half As[2][32][24];   // 16 K-cols + pad to 24 (48B stride)
    __shared__ uint4 Bs[2][256];       // 8 n * 32 lanes, hi/lo per uint4

    const int m0 = blockIdx.x * 32;
    const int split = blockIdx.y;
    const int ks0 = split * FC_KS_PER;
    const int tid = threadIdx.x;
    const int warp = tid >> 5, lane = tid & 31;
    const int mt = warp >> 2, nq = warp & 3;
    const int qid = lane >> 2, tq = lane & 3;

    const int ar = tid >> 1, ap = tid & 1;   // A loader: threads 0..63

    float acc[2][4] = {};
    uint4 a_reg, b_reg;

    // preload chunk 0
    if (tid < 64)
        a_reg = *(const uint4*)&g_conv_out[(size_t)(m0 + ar) * FCK + ks0 * 16 + ap * 8];
    b_reg = g_wfc[(size_t)ks0 * 256 + tid];
    if (tid < 64) *(uint4*)&As[0][ar][ap * 8] = a_reg;
    Bs[0][tid] = b_reg;
    __syncthreads();

    for (int i = 0; i < FC_KS_PER; ++i) {
        const int buf = i & 1;
        // prefetch chunk i+1
        if (i + 1 < FC_KS_PER) {
            const int ks = ks0 + i + 1;
            if (tid < 64)
                a_reg = *(const uint4*)&g_conv_out[(size_t)(m0 + ar) * FCK + ks * 16 + ap * 8];
            b_reg = g_wfc[(size_t)ks * 256 + tid];
        }
        // mma on chunk i
        {
            const int r0 = mt * 16 + qid;
            const int cb = 2 * tq;
            unsigned a0 = *(const unsigned*)&As[buf][r0][cb];
            unsigned a1 = *(const unsigned*)&As[buf][r0 + 8][cb];
            unsigned a2 = *(const unsigned*)&As[buf][r0][cb + 8];
            unsigned a3 = *(const unsigned*)&As[buf][r0 + 8][cb + 8];
#pragma unroll
            for (int j = 0; j < 2; ++j) {
                int n = nq * 2 + j;
                uint4 bb = Bs[buf][n * 32 + lane];
                mma_f16(acc[j], a0, a1, a2, a3, bb.x, bb.y);
                mma_f16(acc[j], a0, a1, a2, a3, bb.z, bb.w);
            }
        }
        // store prefetched chunk into the other buffer
        if (i + 1 < FC_KS_PER) {
            if (tid < 64) *(uint4*)&As[1 - buf][ar][ap * 8] = a_reg;
            Bs[1 - buf][tid] = b_reg;
        }
        __syncthreads();
    }

    // epilogue: raw partial sums
    float* dst = g_fc_part + (size_t)split * FRAMES * 64;
#pragma unroll
    for (int j = 0; j < 2; ++j) {
        const int col = (nq * 2 + j) * 8 + 2 * tq;
#pragma unroll
        for (int half = 0; half < 2; ++half) {
            int m = m0 + mt * 16 + qid + 8 * half;
            dst[(size_t)m * 64 + col]     = acc[j][2 * half];
            dst[(size_t)m * 64 + col + 1] = acc[j][2 * half + 1];
        }
    }
}

// =====================================================================
// Kernel 3: xg = relu(sum(fc partials) + fc_b) @ w_ih^T + b_ih + b_hh
// =====================================================================
__global__ __launch_bounds__(256)
void xgates_kernel(const float* __restrict__ w_ih, const float* __restrict__ fc_b,
                   const float* __restrict__ b_ih, const float* __restrict__ b_hh)
{
    __shared__ float fs[64][64];
    const int f0 = blockIdx.x * 64;
    const int g = threadIdx.x;
    float w[64];
#pragma unroll
    for (int k = 0; k < 64; ++k) w[k] = w_ih[g * 64 + k];
    for (int i = g; i < 64 * 64; i += 256) {
        size_t idx = (size_t)f0 * 64 + i;
        float v = g_fc_part[idx]
                + g_fc_part[(size_t)FRAMES * 64 + idx]
                + g_fc_part[(size_t)2 * FRAMES * 64 + idx]
                + g_fc_part[(size_t)3 * FRAMES * 64 + idx]
                + fc_b[i % 64];
        fs[i / 64][i % 64] = fmaxf(v, 0.f);
    }
    __syncthreads();
    const float bias = b_ih[g] + b_hh[g];
    for (int f = 0; f < 64; ++f) {
        float s = bias;
#pragma unroll
        for (int k = 0; k < 64; ++k) s = fmaf(w[k], fs[f][k], s);
        g_xg[(size_t)(f0 + f) * 256 + g] = s;
    }
}

// =====================================================================
// Kernel 4: recurrent LSTM. 32 CTAs, 512 threads; gate dot split over 2 lanes.
// =====================================================================
__global__ __launch_bounds__(512)
void lstm_kernel(const float* __restrict__ w_hh)
{
    __shared__ float h_s[64];
    __shared__ float g_s[256];
    const int b = blockIdx.x;
    const int tid = threadIdx.x;
    const int g = tid >> 1, hh = tid & 1;

    float w[32];
#pragma unroll
    for (int k = 0; k < 32; ++k) w[k] = w_hh[g * 64 + hh * 32 + k];
    float c = 0.f;
    if (tid < 64) h_s[tid] = 0.f;
    __syncthreads();

    const float* xgb = g_xg + (size_t)b * 128 * 256;
    float* lob = g_lstm + (size_t)b * 128 * 64;

    float xnext = (hh == 0) ? xgb[g] : 0.f;
    for (int t = 0; t < 128; ++t) {
        float s1 = 0.f, s2 = 0.f;
        const float* hp = h_s + hh * 32;
#pragma unroll
        for (int k = 0; k < 16; ++k) {
            s1 = fmaf(w[k], hp[k], s1);
            s2 = fmaf(w[k + 16], hp[k + 16], s2);
        }
        float s = xnext + s1 + s2;
        s += __shfl_xor_sync(0xffffffffu, s, 1);
        if (hh == 0) {
            g_s[g] = s;
            if (t < 127) xnext = xgb[(t + 1) * 256 + g];
        }
        __syncthreads();
        if (tid < 64) {
            float ig = fast_sigmoid(g_s[tid]);
            float fg = fast_sigmoid(g_s[64 + tid]);
            float gg = fast_tanh(g_s[128 + tid]);
            float og = fast_sigmoid(g_s[192 + tid]);
            c = fg * c + ig * gg;
            float h = og * fast_tanh(c);
            lob[t * 64 + tid] = h;
            h_s[tid] = h;
        }
        __syncthreads();
    }
}

// =====================================================================
// Kernel 5: fused policy/value heads
// =====================================================================
__global__ __launch_bounds__(256)
void heads_kernel(const float* __restrict__ p1w, const float* __restrict__ p1b,
                  const float* __restrict__ p2w, const float* __restrict__ p2b,
                  const float* __restrict__ v1w, const float* __restrict__ v1b,
                  const float* __restrict__ v2w, const float* __restrict__ v2b,
                  float* __restrict__ out)
{
    __shared__ float h_s[32][64];
    __shared__ float p2s[6 * 128];
    __shared__ float v2s[128];
    __shared__ float u_s[256];

    const int f0 = blockIdx.x * 32;
    const int t = threadIdx.x;

    const float* wsrc = (t < 128) ? (p1w + t * 64) : (v1w + (t - 128) * 64);
    float w[64];
#pragma unroll
    for (int k = 0; k < 64; ++k) w[k] = wsrc[k];
    const float bias = (t < 128) ? p1b[t] : v1b[t - 128];

    for (int i = t; i < 32 * 64; i += 256) h_s[i / 64][i % 64] = g_lstm[(size_t)f0 * 64 + i];
    for (int i = t; i < 768; i += 256) p2s[i] = p2w[i];
    if (t < 128) v2s[t] = v2w[t];
    __syncthreads();

    const int warp = t >> 5, lane = t & 31;
    for (int fi = 0; fi < 32; ++fi) {
        float s = bias;
#pragma unroll
        for (int k = 0; k < 64; ++k) s = fmaf(w[k], h_s[fi][k], s);
        u_s[t] = fmaxf(s, 0.f);
        __syncthreads();

        const int f = f0 + fi;
        if (warp < 6) {
            float s2 = 0.f;
#pragma unroll
            for (int j = 0; j < 4; ++j)
                s2 = fmaf(p2s[warp * 128 + j * 32 + lane], u_s[j * 32 + lane], s2);
            for (int off = 16; off; off >>= 1) s2 += __shfl_down_sync(0xffffffffu, s2, off);
            if (lane == 0) out[f * 6 + warp] = s2 + p2b[warp];
        } else if (warp == 6) {
            float s2 = 0.f;
#pragma unroll
            for (int j = 0; j < 4; ++j)
                s2 = fmaf(v2s[j * 32 + lane], u_s[128 + j * 32 + lane], s2);
            for (int off = 16; off; off >>= 1) s2 += __shfl_down_sync(0xffffffffu, s2, off);
            if (lane == 0) out[FRAMES * 6 + f] = s2 + v2b[0];
        }
        __syncthreads();
    }
}

// =====================================================================
extern "C" void kernel_launch(void* const* d_in, const int* in_sizes, int n_in,
                              void* d_out, int out_size)
{
    const float* x    = (const float*)d_in[0];
    const float* c0w  = (const float*)d_in[1];
    const float* c0b  = (const float*)d_in[2];
    const float* cws  = (const float*)d_in[3];
    const float* cbs  = (const float*)d_in[4];
    const float* fcw  = (const float*)d_in[5];
    const float* fcb  = (const float*)d_in[6];
    const float* wih  = (const float*)d_in[7];
    const float* whh  = (const float*)d_in[8];
    const float* bih  = (const float*)d_in[9];
    const float* bhh  = (const float*)d_in[10];
    const float* p1w  = (const float*)d_in[11];
    const float* p1b  = (const float*)d_in[12];
    const float* p2w  = (const float*)d_in[13];
    const float* p2b  = (const float*)d_in[14];
    const float* v1w  = (const float*)d_in[15];
    const float* v1b  = (const float*)d_in[16];
    const float* v2w  = (const float*)d_in[17];
    const float* v2b  = (const float*)d_in[18];
    float* out = (float*)d_out;

    const int conv_smem = XROWS * XSTRIDE * 2 + BFRAGS * 8 + 256;
    cudaFuncSetAttribute(conv_mma_kernel,
                         cudaFuncAttributeMaxDynamicSharedMemorySize, conv_smem);

    bfrag_prep<<<288, 256>>>(c0w, cws);
    wfrag_prep<<<(FC_KS * 8 * 32 + 255) / 256, 256>>>(fcw);
    conv_mma_kernel<<<FRAMES, 288, conv_smem>>>(x, c0b, cbs);
    fc_mma_kernel<<<dim3(FRAMES / 32, FC_SPLITS), 256>>>();
    xgates_kernel<<<FRAMES / 64, 256>>>(wih, fcb, bih, bhh);
    lstm_kernel<<<32, 512>>>(whh);
    heads_kernel<<<FRAMES / 32, 256>>>(p1w, p1b, p2w, p2b, v1w, v1b, v2w, v2b, out);
}